// round 1
// baseline (speedup 1.0000x reference)
#include <cuda_runtime.h>
#include <math.h>
#include <stdint.h>

// Problem constants
#define BB 16
#define SS 1024
#define DD 1024
#define HH 16
#define DK 64
#define MTOK (BB*SS)          // 16384 token rows

// Scratch buffers (device globals — no allocation allowed)
__device__ float g_A[(size_t)MTOK * DD];
__device__ float g_B[(size_t)MTOK * DD];
__device__ float g_C[(size_t)MTOK * DD];
__device__ float g_D[(size_t)MTOK * DD];

// ---------------------------------------------------------------------------
// Tiled SGEMM: C[M,N] = A[M,K] @ B  (+bias, +relu)
// B is [K,N] normally, [N,K] when TRANSB (i.e. C = A @ B^T)
// BM=BN=64, BK=16, 256 threads, 4x4 micro-tile per thread.
// ---------------------------------------------------------------------------
template<bool TRANSB, bool BIAS, bool RELU>
__global__ void __launch_bounds__(256) sgemm64(
    const float* __restrict__ A, const float* __restrict__ Bm,
    const float* __restrict__ bias, float* __restrict__ C,
    int M, int N, int K)
{
    __shared__ float As[16][68];
    __shared__ float Bs[16][68];

    const int tid = threadIdx.x;
    const int tx = tid & 15;
    const int ty = tid >> 4;
    const int n0 = blockIdx.x * 64;
    const int m0 = blockIdx.y * 64;

    float acc[4][4] = {};

    for (int k0 = 0; k0 < K; k0 += 16) {
        // Load A tile (64 x 16), stored transposed As[k][m]
        {
            const int m  = tid >> 2;
            const int k4 = tid & 3;
            const float4 v = *(const float4*)(A + (size_t)(m0 + m) * K + k0 + k4 * 4);
            As[k4*4+0][m] = v.x; As[k4*4+1][m] = v.y;
            As[k4*4+2][m] = v.z; As[k4*4+3][m] = v.w;
        }
        if (TRANSB) {
            // B is [N,K]; need Bs[k][n]
            const int n  = tid >> 2;
            const int k4 = tid & 3;
            const float4 v = *(const float4*)(Bm + (size_t)(n0 + n) * K + k0 + k4 * 4);
            Bs[k4*4+0][n] = v.x; Bs[k4*4+1][n] = v.y;
            Bs[k4*4+2][n] = v.z; Bs[k4*4+3][n] = v.w;
        } else {
            // B is [K,N]; direct rows
            const int k  = tid >> 4;
            const int n4 = tid & 15;
            *(float4*)&Bs[k][n4*4] =
                *(const float4*)(Bm + (size_t)(k0 + k) * N + n0 + n4 * 4);
        }
        __syncthreads();

        #pragma unroll
        for (int k = 0; k < 16; k++) {
            const float4 a = *(const float4*)&As[k][ty * 4];
            const float4 b = *(const float4*)&Bs[k][tx * 4];
            const float av[4] = {a.x, a.y, a.z, a.w};
            const float bv[4] = {b.x, b.y, b.z, b.w};
            #pragma unroll
            for (int i = 0; i < 4; i++)
                #pragma unroll
                for (int j = 0; j < 4; j++)
                    acc[i][j] += av[i] * bv[j];
        }
        __syncthreads();
    }

    float4 bv4 = make_float4(0.f, 0.f, 0.f, 0.f);
    if (BIAS) bv4 = *(const float4*)(bias + n0 + tx * 4);

    #pragma unroll
    for (int i = 0; i < 4; i++) {
        float4 r;
        r.x = acc[i][0]; r.y = acc[i][1]; r.z = acc[i][2]; r.w = acc[i][3];
        if (BIAS) { r.x += bv4.x; r.y += bv4.y; r.z += bv4.z; r.w += bv4.w; }
        if (RELU) {
            r.x = fmaxf(r.x, 0.f); r.y = fmaxf(r.y, 0.f);
            r.z = fmaxf(r.z, 0.f); r.w = fmaxf(r.w, 0.f);
        }
        *(float4*)(C + (size_t)(m0 + ty * 4 + i) * N + n0 + tx * 4) = r;
    }
}

// ---------------------------------------------------------------------------
// Flash-style causal attention for one (b,h,q-tile of 64).
// Heads live in columns h*64..h*64+63 of the projected (MTOK x D) buffers.
// Online softmax, 64x64 tiles, 4x4 register micro-tiles.
// ---------------------------------------------------------------------------
#define SMSTRIDE 68
__global__ void __launch_bounds__(256) attn_kernel(
    const float* __restrict__ Qp, const float* __restrict__ Kp,
    const float* __restrict__ Vp, const unsigned char* __restrict__ mask,
    float* __restrict__ ctx)
{
    extern __shared__ float sh[];
    float* Qst = sh;                       // [64][68]  d-major: Qst[d][m]
    float* Kst = sh + 64 * SMSTRIDE;       // [64][68]  d-major: Kst[d][k]
    float* Vs  = sh + 2 * 64 * SMSTRIDE;   // [64][68]  k-major: Vs[k][d]
    float* Ps  = sh + 3 * 64 * SMSTRIDE;   // [64][68]  k-major: Ps[k][m]

    const int tid = threadIdx.x;
    const int tx = tid & 15;
    const int ty = tid >> 4;
    const int qt = blockIdx.x;             // q tile (0..15)
    const int bh = blockIdx.y;             // 0..255
    const int b = bh >> 4;
    const int h = bh & 15;

    const size_t base = (size_t)b * SS * DD + (size_t)h * DK;
    const float* Qb = Qp + base + (size_t)qt * 64 * DD;

    // Load Q tile transposed
    #pragma unroll
    for (int r = 0; r < 4; r++) {
        const int e = tid + r * 256;
        const int m = e >> 4, d4 = e & 15;
        const float4 v = *(const float4*)(Qb + (size_t)m * DD + d4 * 4);
        Qst[(d4*4+0)*SMSTRIDE + m] = v.x; Qst[(d4*4+1)*SMSTRIDE + m] = v.y;
        Qst[(d4*4+2)*SMSTRIDE + m] = v.z; Qst[(d4*4+3)*SMSTRIDE + m] = v.w;
    }

    unsigned char pmask[4];
    float mrow[4], lrow[4], o[4][4] = {};
    #pragma unroll
    for (int i = 0; i < 4; i++) {
        pmask[i] = mask[(size_t)b * SS + qt * 64 + ty * 4 + i];
        mrow[i] = -1e30f;
        lrow[i] = 0.f;
    }

    const float NEGV  = -4294967295.0f;            // torch masked_fill value
    const float scale = 1.0f / 8.000001f;          // 1/(sqrt(64)+1e-6)

    for (int kt = 0; kt <= qt; kt++) {
        __syncthreads();   // prior iter done with Kst/Vs/Ps
        const float* Kb = Kp + base + (size_t)kt * 64 * DD;
        const float* Vb = Vp + base + (size_t)kt * 64 * DD;
        #pragma unroll
        for (int r = 0; r < 4; r++) {
            const int e = tid + r * 256;
            const int m = e >> 4, d4 = e & 15;
            const float4 v = *(const float4*)(Kb + (size_t)m * DD + d4 * 4);
            Kst[(d4*4+0)*SMSTRIDE + m] = v.x; Kst[(d4*4+1)*SMSTRIDE + m] = v.y;
            Kst[(d4*4+2)*SMSTRIDE + m] = v.z; Kst[(d4*4+3)*SMSTRIDE + m] = v.w;
            const float4 w = *(const float4*)(Vb + (size_t)m * DD + d4 * 4);
            *(float4*)&Vs[m * SMSTRIDE + d4 * 4] = w;
        }
        __syncthreads();

        // Scores S = Q @ K^T for this 64x64 tile
        float s[4][4] = {};
        #pragma unroll 8
        for (int d = 0; d < 64; d++) {
            const float4 a = *(const float4*)&Qst[d * SMSTRIDE + ty * 4];
            const float4 k4 = *(const float4*)&Kst[d * SMSTRIDE + tx * 4];
            const float av[4] = {a.x, a.y, a.z, a.w};
            const float kv[4] = {k4.x, k4.y, k4.z, k4.w};
            #pragma unroll
            for (int i = 0; i < 4; i++)
                #pragma unroll
                for (int j = 0; j < 4; j++)
                    s[i][j] += av[i] * kv[j];
        }

        const bool diag = (kt == qt);
        #pragma unroll
        for (int i = 0; i < 4; i++) {
            const int ql = ty * 4 + i;
            #pragma unroll
            for (int j = 0; j < 4; j++) {
                s[i][j] *= scale;
                const int kl = tx * 4 + j;
                if ((diag && kl > ql) || pmask[i]) s[i][j] = NEGV;
            }
        }

        // Online softmax update (row spread across 16 lanes of a half-warp)
        #pragma unroll
        for (int i = 0; i < 4; i++) {
            float tmax = fmaxf(fmaxf(s[i][0], s[i][1]), fmaxf(s[i][2], s[i][3]));
            #pragma unroll
            for (int off = 8; off; off >>= 1)
                tmax = fmaxf(tmax, __shfl_xor_sync(0xffffffffu, tmax, off));
            const float mnew = fmaxf(mrow[i], tmax);
            const float f = __expf(mrow[i] - mnew);
            float ps = 0.f;
            #pragma unroll
            for (int j = 0; j < 4; j++) {
                const float p = __expf(s[i][j] - mnew);
                s[i][j] = p;
                ps += p;
                o[i][j] *= f;
            }
            #pragma unroll
            for (int off = 8; off; off >>= 1)
                ps += __shfl_xor_sync(0xffffffffu, ps, off);
            lrow[i] = lrow[i] * f + ps;
            mrow[i] = mnew;
        }

        // Write P transposed: Ps[k][m]
        #pragma unroll
        for (int i = 0; i < 4; i++)
            #pragma unroll
            for (int j = 0; j < 4; j++)
                Ps[(tx * 4 + j) * SMSTRIDE + ty * 4 + i] = s[i][j];
        __syncthreads();

        // O += P @ V
        #pragma unroll 8
        for (int k = 0; k < 64; k++) {
            const float4 a = *(const float4*)&Ps[k * SMSTRIDE + ty * 4];
            const float4 v4 = *(const float4*)&Vs[k * SMSTRIDE + tx * 4];
            const float av[4] = {a.x, a.y, a.z, a.w};
            const float vv[4] = {v4.x, v4.y, v4.z, v4.w};
            #pragma unroll
            for (int i = 0; i < 4; i++)
                #pragma unroll
                for (int j = 0; j < 4; j++)
                    o[i][j] += av[i] * vv[j];
        }
    }

    // Normalize and write ctx (B,S,D layout, head columns)
    #pragma unroll
    for (int i = 0; i < 4; i++) {
        const float inv = 1.0f / lrow[i];
        const int qg = qt * 64 + ty * 4 + i;
        float4 r;
        r.x = o[i][0] * inv; r.y = o[i][1] * inv;
        r.z = o[i][2] * inv; r.w = o[i][3] * inv;
        *(float4*)(ctx + ((size_t)b * SS + qg) * DD + h * DK + tx * 4) = r;
    }
}

// ---------------------------------------------------------------------------
// out[row] = LayerNorm(X[row] + R[row]) * w + b     (one block per row)
// ---------------------------------------------------------------------------
__global__ void __launch_bounds__(256) add_ln_kernel(
    const float* __restrict__ X, const float* __restrict__ R,
    const float* __restrict__ w, const float* __restrict__ bb,
    float* __restrict__ out)
{
    const int row = blockIdx.x;
    const int tid = threadIdx.x;
    const float4* x4 = (const float4*)(X + (size_t)row * DD);
    const float4* r4 = (const float4*)(R + (size_t)row * DD);
    float4 v = x4[tid];
    const float4 r = r4[tid];
    v.x += r.x; v.y += r.y; v.z += r.z; v.w += r.w;

    float sum = v.x + v.y + v.z + v.w;
    float sq  = v.x*v.x + v.y*v.y + v.z*v.z + v.w*v.w;
    #pragma unroll
    for (int off = 16; off; off >>= 1) {
        sum += __shfl_xor_sync(0xffffffffu, sum, off);
        sq  += __shfl_xor_sync(0xffffffffu, sq, off);
    }
    __shared__ float ssum[8], ssq[8];
    if ((tid & 31) == 0) { ssum[tid >> 5] = sum; ssq[tid >> 5] = sq; }
    __syncthreads();
    float tot = 0.f, totq = 0.f;
    #pragma unroll
    for (int i = 0; i < 8; i++) { tot += ssum[i]; totq += ssq[i]; }
    const float mu   = tot * (1.0f / DD);
    const float var  = totq * (1.0f / DD) - mu * mu;
    const float rstd = rsqrtf(var + 1e-5f);

    const float4 wv = ((const float4*)w)[tid];
    const float4 bv = ((const float4*)bb)[tid];
    float4 ov;
    ov.x = (v.x - mu) * rstd * wv.x + bv.x;
    ov.y = (v.y - mu) * rstd * wv.y + bv.y;
    ov.z = (v.z - mu) * rstd * wv.z + bv.z;
    ov.w = (v.w - mu) * rstd * wv.w + bv.w;
    ((float4*)(out + (size_t)row * DD))[tid] = ov;
}

// ---------------------------------------------------------------------------
extern "C" void kernel_launch(void* const* d_in, const int* in_sizes, int n_in,
                              void* d_out, int out_size)
{
    // Resolve input order: mask is the only 16384-element input.
    int mi = -1;
    for (int i = 0; i < n_in; i++)
        if (in_sizes[i] == BB * SS) { mi = i; break; }

    const float *Q, *K, *V, *Wq, *Wk, *Wv, *Wo, *l1w, *l1b, *l2w, *l2b, *lnw, *lnb;
    const unsigned char* mask;
    if (mi == 3) {
        // setup_inputs dict order
        Q   = (const float*)d_in[0];  K   = (const float*)d_in[1];
        V   = (const float*)d_in[2];  mask = (const unsigned char*)d_in[3];
        Wq  = (const float*)d_in[4];  Wk  = (const float*)d_in[5];
        Wv  = (const float*)d_in[6];  Wo  = (const float*)d_in[7];
        l1w = (const float*)d_in[8];  l1b = (const float*)d_in[9];
        l2w = (const float*)d_in[10]; l2b = (const float*)d_in[11];
        lnw = (const float*)d_in[12]; lnb = (const float*)d_in[13];
    } else {
        // reference() signature order (mask last)
        Q   = (const float*)d_in[0];  K   = (const float*)d_in[1];
        V   = (const float*)d_in[2];
        Wq  = (const float*)d_in[3];  Wk  = (const float*)d_in[4];
        Wv  = (const float*)d_in[5];  Wo  = (const float*)d_in[6];
        l1w = (const float*)d_in[7];  l1b = (const float*)d_in[8];
        l2w = (const float*)d_in[9];  l2b = (const float*)d_in[10];
        lnw = (const float*)d_in[11]; lnb = (const float*)d_in[12];
        mask = (const unsigned char*)d_in[13];
    }

    float *gA, *gB, *gC, *gD;
    cudaGetSymbolAddress((void**)&gA, g_A);
    cudaGetSymbolAddress((void**)&gB, g_B);
    cudaGetSymbolAddress((void**)&gC, g_C);
    cudaGetSymbolAddress((void**)&gD, g_D);

    const dim3 gGrid(DD / 64, MTOK / 64);   // (16, 256)

    // QKV projections
    sgemm64<false, false, false><<<gGrid, 256>>>(Q, Wq, nullptr, gA, MTOK, DD, DD);
    sgemm64<false, false, false><<<gGrid, 256>>>(K, Wk, nullptr, gB, MTOK, DD, DD);
    sgemm64<false, false, false><<<gGrid, 256>>>(V, Wv, nullptr, gC, MTOK, DD, DD);

    // Attention
    const int shmem = 4 * 64 * SMSTRIDE * (int)sizeof(float);   // 69632 B
    cudaFuncSetAttribute(attn_kernel, cudaFuncAttributeMaxDynamicSharedMemorySize, shmem);
    attn_kernel<<<dim3(SS / 64, BB * HH), 256, shmem>>>(gA, gB, gC, mask, gD);

    // Output projection
    sgemm64<false, false, false><<<gGrid, 256>>>(gD, Wo, nullptr, gA, MTOK, DD, DD);
    // X = LN(V_att + Q)
    add_ln_kernel<<<MTOK, 256>>>(gA, Q, lnw, lnb, gB);
    // FFN
    sgemm64<true, true, true ><<<gGrid, 256>>>(gB, l1w, l1b, gC, MTOK, DD, DD);
    sgemm64<true, true, false><<<gGrid, 256>>>(gC, l2w, l2b, gD, MTOK, DD, DD);
    // out = LN(ffn + X)
    add_ln_kernel<<<MTOK, 256>>>(gD, gB, lnw, lnb, (float*)d_out);
}

// round 6
// speedup vs baseline: 1.6408x; 1.6408x over previous
#include <cuda_runtime.h>
#include <cuda_bf16.h>
#include <math.h>
#include <stdint.h>

// Problem constants
#define BB 16
#define SS 1024
#define DD 1024
#define HH 16
#define DK 64
#define MTOK (BB*SS)          // 16384 token rows

// Scratch buffers (device globals — no allocation allowed)
__device__ float g_A[(size_t)MTOK * DD];
__device__ float g_B[(size_t)MTOK * DD];
__device__ float g_C[(size_t)MTOK * DD];
__device__ float g_D[(size_t)MTOK * DD];

// ===========================================================================
// Baseline-PTX tensor core helpers (work on plain sm_103 target: no 'a' feats)
// ===========================================================================
__device__ __forceinline__ uint32_t smem_u32(const void* p) {
    uint32_t a;
    asm("{ .reg .u64 t; cvta.to.shared.u64 t, %1; cvt.u32.u64 %0, t; }" : "=r"(a) : "l"(p));
    return a;
}

#define LDSM_X4(R0, R1, R2, R3, addr)                                          \
    asm volatile("ldmatrix.sync.aligned.m8n8.x4.shared.b16 {%0,%1,%2,%3}, [%4];" \
        : "=r"(R0), "=r"(R1), "=r"(R2), "=r"(R3) : "r"(addr))

__device__ __forceinline__ void mma16816(float* d, const uint32_t* a, const uint32_t* b) {
    asm volatile(
        "mma.sync.aligned.m16n8k16.row.col.f32.bf16.bf16.f32 "
        "{%0,%1,%2,%3}, {%4,%5,%6,%7}, {%8,%9}, {%0,%1,%2,%3};"
        : "+f"(d[0]), "+f"(d[1]), "+f"(d[2]), "+f"(d[3])
        : "r"(a[0]), "r"(a[1]), "r"(a[2]), "r"(a[3]), "r"(b[0]), "r"(b[1]));
}

// bf16 split: hi+lo decomposition packed along k (lower 16 bits = first k)
__device__ __forceinline__ void split2(float a, float b, uint32_t& hi, uint32_t& lo) {
    __nv_bfloat16 ah = __float2bfloat16_rn(a);
    __nv_bfloat16 bh = __float2bfloat16_rn(b);
    __nv_bfloat16 al = __float2bfloat16_rn(a - __bfloat162float(ah));
    __nv_bfloat16 bl = __float2bfloat16_rn(b - __bfloat162float(bh));
    hi = (uint32_t)__bfloat16_as_ushort(ah) | ((uint32_t)__bfloat16_as_ushort(bh) << 16);
    lo = (uint32_t)__bfloat16_as_ushort(al) | ((uint32_t)__bfloat16_as_ushort(bl) << 16);
}

// ===========================================================================
// Split-bf16 mma.sync GEMM: C[16384,1024] = A[16384,1024] @ B (+bias,+relu)
// B is [K,N] normally; [N,K] when TRANSB (C = A @ B^T).
// CTA 128x128, BK=32. 8 warps in 4(M) x 2(N); warp tile 32x64.
// SMEM tiles padded to 40 bf16 (80B) row stride -> conflict-free ldmatrix.
// Double-buffered stages with register-staged global prefetch.
// ===========================================================================
#define RSTRIDE 80                         // bytes per smem row (40 bf16)
#define T_BYTES (128 * RSTRIDE)            // one tile (hi or lo): 10240 B
#define STG_BYTES (4 * T_BYTES)            // Ah, Al, Bh, Bl: 40960 B
#define GEMM_SMEM (2 * STG_BYTES)          // 81920 B
#define NCHUNK (DD / 32)                   // 32

template<bool TRANSB, bool BIAS, bool RELU>
__global__ void __launch_bounds__(256, 1) mma_gemm(
    const float* __restrict__ A, const float* __restrict__ Bm,
    const float* __restrict__ bias, float* __restrict__ C)
{
    extern __shared__ char smem[];
    const uint32_t sbase = smem_u32(smem);
    const int tid  = threadIdx.x;
    const int lane = tid & 31;
    const int wid  = tid >> 5;
    const int wm   = wid & 3;              // 4 M-warps * 32 rows
    const int wn   = wid >> 2;             // 2 N-warps * 64 cols
    const int n0   = blockIdx.x * 128;
    const int m0   = blockIdx.y * 128;

    float acc[2][8][4] = {};
    float4 rA[4], rB[4];

    // ---- global load (prefetch into regs) ----
    auto ldA = [&](int k0) {
        #pragma unroll
        for (int i = 0; i < 4; i++) {
            const int t = tid + 256 * i;
            const int row = t >> 3, kg = t & 7;
            rA[i] = *(const float4*)(A + (size_t)(m0 + row) * DD + k0 + kg * 4);
        }
    };
    auto ldB = [&](int k0) {
        if (TRANSB) {
            #pragma unroll
            for (int i = 0; i < 4; i++) {
                const int t = tid + 256 * i;
                const int row = t >> 3, kg = t & 7;
                rB[i] = *(const float4*)(Bm + (size_t)(n0 + row) * DD + k0 + kg * 4);
            }
        } else {
            #pragma unroll
            for (int i = 0; i < 2; i++) {
                const int t = tid + 256 * i;
                const int kp = t >> 5, ng = t & 31;
                rB[2*i]   = *(const float4*)(Bm + (size_t)(k0 + 2*kp)     * DD + n0 + ng * 4);
                rB[2*i+1] = *(const float4*)(Bm + (size_t)(k0 + 2*kp + 1) * DD + n0 + ng * 4);
            }
        }
    };
    // ---- convert + store regs -> smem stage ----
    auto stA = [&](char* stg) {
        char* hi = stg;             // Ah at 0
        char* lo = stg + T_BYTES;   // Al
        #pragma unroll
        for (int i = 0; i < 4; i++) {
            const int t = tid + 256 * i;
            const int row = t >> 3, kg = t & 7;
            uint32_t h0, l0, h1, l1;
            split2(rA[i].x, rA[i].y, h0, l0);
            split2(rA[i].z, rA[i].w, h1, l1);
            const int b = row * RSTRIDE + kg * 8;
            *(uint32_t*)(hi + b)     = h0;  *(uint32_t*)(hi + b + 4) = h1;
            *(uint32_t*)(lo + b)     = l0;  *(uint32_t*)(lo + b + 4) = l1;
        }
    };
    auto stB = [&](char* stg) {
        char* hi = stg + 2 * T_BYTES;   // Bh
        char* lo = stg + 3 * T_BYTES;   // Bl
        if (TRANSB) {
            #pragma unroll
            for (int i = 0; i < 4; i++) {
                const int t = tid + 256 * i;
                const int row = t >> 3, kg = t & 7;
                uint32_t h0, l0, h1, l1;
                split2(rB[i].x, rB[i].y, h0, l0);
                split2(rB[i].z, rB[i].w, h1, l1);
                const int b = row * RSTRIDE + kg * 8;
                *(uint32_t*)(hi + b)     = h0;  *(uint32_t*)(hi + b + 4) = h1;
                *(uint32_t*)(lo + b)     = l0;  *(uint32_t*)(lo + b + 4) = l1;
            }
        } else {
            #pragma unroll
            for (int i = 0; i < 2; i++) {
                const int t = tid + 256 * i;
                const int kp = t >> 5, ng = t & 31;
                const float v0[4] = {rB[2*i].x, rB[2*i].y, rB[2*i].z, rB[2*i].w};
                const float v1[4] = {rB[2*i+1].x, rB[2*i+1].y, rB[2*i+1].z, rB[2*i+1].w};
                #pragma unroll
                for (int j = 0; j < 4; j++) {
                    uint32_t h, l;
                    split2(v0[j], v1[j], h, l);     // pack along k: (2kp, 2kp+1)
                    const int n = ng * 4 + j;
                    const int b = n * RSTRIDE + kp * 4;
                    *(uint32_t*)(hi + b) = h;
                    *(uint32_t*)(lo + b) = l;
                }
            }
        }
    };
    // ---- compute one 32-k chunk from smem stage ----
    auto compute = [&](uint32_t stg) {
        const uint32_t sAh = stg;
        const uint32_t sAl = stg + T_BYTES;
        const uint32_t sBh = stg + 2 * T_BYTES;
        const uint32_t sBl = stg + 3 * T_BYTES;
        #pragma unroll
        for (int ks = 0; ks < 2; ks++) {
            const int kb = ks * 16 * 2;                     // byte offset of k
            uint32_t ah[2][4], al[2][4], bh[4][4], bl[4][4];
            const int arow = (lane & 15);
            const int acb  = kb + ((lane >> 4) * 8) * 2;
            #pragma unroll
            for (int mt = 0; mt < 2; mt++) {
                const uint32_t off = (uint32_t)((wm * 32 + mt * 16 + arow) * RSTRIDE + acb);
                LDSM_X4(ah[mt][0], ah[mt][1], ah[mt][2], ah[mt][3], sAh + off);
                LDSM_X4(al[mt][0], al[mt][1], al[mt][2], al[mt][3], sAl + off);
            }
            const int q  = lane >> 3;
            const int lr = lane & 7;
            const int brow_q = ((q & 2) ? 8 : 0) + lr;
            const int bcb    = kb + ((q & 1) * 8) * 2;
            #pragma unroll
            for (int p = 0; p < 4; p++) {
                const uint32_t off = (uint32_t)((wn * 64 + p * 16 + brow_q) * RSTRIDE + bcb);
                LDSM_X4(bh[p][0], bh[p][1], bh[p][2], bh[p][3], sBh + off);
                LDSM_X4(bl[p][0], bl[p][1], bl[p][2], bl[p][3], sBl + off);
            }
            #pragma unroll
            for (int mt = 0; mt < 2; mt++)
                #pragma unroll
                for (int p = 0; p < 4; p++)
                    #pragma unroll
                    for (int h = 0; h < 2; h++) {
                        float* d = acc[mt][p * 2 + h];
                        mma16816(d, ah[mt], &bh[p][h * 2]);
                        mma16816(d, ah[mt], &bl[p][h * 2]);
                        mma16816(d, al[mt], &bh[p][h * 2]);
                    }
        }
    };

    // ---- main loop: double-buffered ----
    ldA(0); ldB(0);
    stA(smem); stB(smem);
    __syncthreads();
    for (int c = 0; c < NCHUNK; c++) {
        const int s = c & 1;
        if (c + 1 < NCHUNK) { ldA((c + 1) * 32); ldB((c + 1) * 32); }
        compute(sbase + s * STG_BYTES);
        if (c + 1 < NCHUNK) { stA(smem + (s ^ 1) * STG_BYTES); stB(smem + (s ^ 1) * STG_BYTES); }
        __syncthreads();
    }

    // ---- epilogue ----
    #pragma unroll
    for (int mt = 0; mt < 2; mt++) {
        const int row = m0 + wm * 32 + mt * 16 + (lane >> 2);
        #pragma unroll
        for (int nt = 0; nt < 8; nt++) {
            const int col = n0 + wn * 64 + nt * 8 + (lane & 3) * 2;
            float b0 = 0.f, b1 = 0.f;
            if (BIAS) { b0 = __ldg(bias + col); b1 = __ldg(bias + col + 1); }
            float2 v01, v23;
            v01.x = acc[mt][nt][0] + b0;  v01.y = acc[mt][nt][1] + b1;
            v23.x = acc[mt][nt][2] + b0;  v23.y = acc[mt][nt][3] + b1;
            if (RELU) {
                v01.x = fmaxf(v01.x, 0.f); v01.y = fmaxf(v01.y, 0.f);
                v23.x = fmaxf(v23.x, 0.f); v23.y = fmaxf(v23.y, 0.f);
            }
            *(float2*)(C + (size_t)row * DD + col)       = v01;
            *(float2*)(C + (size_t)(row + 8) * DD + col) = v23;
        }
    }
}

// ---------------------------------------------------------------------------
// Flash-style causal attention (fp32, unchanged — known good)
// ---------------------------------------------------------------------------
#define SMSTRIDE 68
__global__ void __launch_bounds__(256) attn_kernel(
    const float* __restrict__ Qp, const float* __restrict__ Kp,
    const float* __restrict__ Vp, const unsigned char* __restrict__ mask,
    float* __restrict__ ctx)
{
    extern __shared__ float sh[];
    float* Qst = sh;
    float* Kst = sh + 64 * SMSTRIDE;
    float* Vs  = sh + 2 * 64 * SMSTRIDE;
    float* Ps  = sh + 3 * 64 * SMSTRIDE;

    const int tid = threadIdx.x;
    const int tx = tid & 15;
    const int ty = tid >> 4;
    const int qt = blockIdx.x;
    const int bh = blockIdx.y;
    const int b = bh >> 4;
    const int h = bh & 15;

    const size_t base = (size_t)b * SS * DD + (size_t)h * DK;
    const float* Qb = Qp + base + (size_t)qt * 64 * DD;

    #pragma unroll
    for (int r = 0; r < 4; r++) {
        const int e = tid + r * 256;
        const int m = e >> 4, d4 = e & 15;
        const float4 v = *(const float4*)(Qb + (size_t)m * DD + d4 * 4);
        Qst[(d4*4+0)*SMSTRIDE + m] = v.x; Qst[(d4*4+1)*SMSTRIDE + m] = v.y;
        Qst[(d4*4+2)*SMSTRIDE + m] = v.z; Qst[(d4*4+3)*SMSTRIDE + m] = v.w;
    }

    unsigned char pmask[4];
    float mrow[4], lrow[4], o[4][4] = {};
    #pragma unroll
    for (int i = 0; i < 4; i++) {
        pmask[i] = mask[(size_t)b * SS + qt * 64 + ty * 4 + i];
        mrow[i] = -1e30f;
        lrow[i] = 0.f;
    }

    const float NEGV  = -4294967295.0f;
    const float scale = 1.0f / 8.000001f;

    for (int kt = 0; kt <= qt; kt++) {
        __syncthreads();
        const float* Kb = Kp + base + (size_t)kt * 64 * DD;
        const float* Vb = Vp + base + (size_t)kt * 64 * DD;
        #pragma unroll
        for (int r = 0; r < 4; r++) {
            const int e = tid + r * 256;
            const int m = e >> 4, d4 = e & 15;
            const float4 v = *(const float4*)(Kb + (size_t)m * DD + d4 * 4);
            Kst[(d4*4+0)*SMSTRIDE + m] = v.x; Kst[(d4*4+1)*SMSTRIDE + m] = v.y;
            Kst[(d4*4+2)*SMSTRIDE + m] = v.z; Kst[(d4*4+3)*SMSTRIDE + m] = v.w;
            const float4 w = *(const float4*)(Vb + (size_t)m * DD + d4 * 4);
            *(float4*)&Vs[m * SMSTRIDE + d4 * 4] = w;
        }
        __syncthreads();

        float s[4][4] = {};
        #pragma unroll 8
        for (int d = 0; d < 64; d++) {
            const float4 a = *(const float4*)&Qst[d * SMSTRIDE + ty * 4];
            const float4 k4 = *(const float4*)&Kst[d * SMSTRIDE + tx * 4];
            const float av[4] = {a.x, a.y, a.z, a.w};
            const float kv[4] = {k4.x, k4.y, k4.z, k4.w};
            #pragma unroll
            for (int i = 0; i < 4; i++)
                #pragma unroll
                for (int j = 0; j < 4; j++)
                    s[i][j] += av[i] * kv[j];
        }

        const bool diag = (kt == qt);
        #pragma unroll
        for (int i = 0; i < 4; i++) {
            const int ql = ty * 4 + i;
            #pragma unroll
            for (int j = 0; j < 4; j++) {
                s[i][j] *= scale;
                const int kl = tx * 4 + j;
                if ((diag && kl > ql) || pmask[i]) s[i][j] = NEGV;
            }
        }

        #pragma unroll
        for (int i = 0; i < 4; i++) {
            float tmax = fmaxf(fmaxf(s[i][0], s[i][1]), fmaxf(s[i][2], s[i][3]));
            #pragma unroll
            for (int off = 8; off; off >>= 1)
                tmax = fmaxf(tmax, __shfl_xor_sync(0xffffffffu, tmax, off));
            const float mnew = fmaxf(mrow[i], tmax);
            const float f = __expf(mrow[i] - mnew);
            float ps = 0.f;
            #pragma unroll
            for (int j = 0; j < 4; j++) {
                const float p = __expf(s[i][j] - mnew);
                s[i][j] = p;
                ps += p;
                o[i][j] *= f;
            }
            #pragma unroll
            for (int off = 8; off; off >>= 1)
                ps += __shfl_xor_sync(0xffffffffu, ps, off);
            lrow[i] = lrow[i] * f + ps;
            mrow[i] = mnew;
        }

        #pragma unroll
        for (int i = 0; i < 4; i++)
            #pragma unroll
            for (int j = 0; j < 4; j++)
                Ps[(tx * 4 + j) * SMSTRIDE + ty * 4 + i] = s[i][j];
        __syncthreads();

        #pragma unroll 8
        for (int k = 0; k < 64; k++) {
            const float4 a = *(const float4*)&Ps[k * SMSTRIDE + ty * 4];
            const float4 v4 = *(const float4*)&Vs[k * SMSTRIDE + tx * 4];
            const float av[4] = {a.x, a.y, a.z, a.w};
            const float vv[4] = {v4.x, v4.y, v4.z, v4.w};
            #pragma unroll
            for (int i = 0; i < 4; i++)
                #pragma unroll
                for (int j = 0; j < 4; j++)
                    o[i][j] += av[i] * vv[j];
        }
    }

    #pragma unroll
    for (int i = 0; i < 4; i++) {
        const float inv = 1.0f / lrow[i];
        const int qg = qt * 64 + ty * 4 + i;
        float4 r;
        r.x = o[i][0] * inv; r.y = o[i][1] * inv;
        r.z = o[i][2] * inv; r.w = o[i][3] * inv;
        *(float4*)(ctx + ((size_t)b * SS + qg) * DD + h * DK + tx * 4) = r;
    }
}

// ---------------------------------------------------------------------------
// out[row] = LayerNorm(X[row] + R[row]) * w + b
// ---------------------------------------------------------------------------
__global__ void __launch_bounds__(256) add_ln_kernel(
    const float* __restrict__ X, const float* __restrict__ R,
    const float* __restrict__ w, const float* __restrict__ bb,
    float* __restrict__ out)
{
    const int row = blockIdx.x;
    const int tid = threadIdx.x;
    const float4* x4 = (const float4*)(X + (size_t)row * DD);
    const float4* r4 = (const float4*)(R + (size_t)row * DD);
    float4 v = x4[tid];
    const float4 r = r4[tid];
    v.x += r.x; v.y += r.y; v.z += r.z; v.w += r.w;

    float sum = v.x + v.y + v.z + v.w;
    float sq  = v.x*v.x + v.y*v.y + v.z*v.z + v.w*v.w;
    #pragma unroll
    for (int off = 16; off; off >>= 1) {
        sum += __shfl_xor_sync(0xffffffffu, sum, off);
        sq  += __shfl_xor_sync(0xffffffffu, sq, off);
    }
    __shared__ float ssum[8], ssq[8];
    if ((tid & 31) == 0) { ssum[tid >> 5] = sum; ssq[tid >> 5] = sq; }
    __syncthreads();
    float tot = 0.f, totq = 0.f;
    #pragma unroll
    for (int i = 0; i < 8; i++) { tot += ssum[i]; totq += ssq[i]; }
    const float mu   = tot * (1.0f / DD);
    const float var  = totq * (1.0f / DD) - mu * mu;
    const float rstd = rsqrtf(var + 1e-5f);

    const float4 wv = ((const float4*)w)[tid];
    const float4 bv = ((const float4*)bb)[tid];
    float4 ov;
    ov.x = (v.x - mu) * rstd * wv.x + bv.x;
    ov.y = (v.y - mu) * rstd * wv.y + bv.y;
    ov.z = (v.z - mu) * rstd * wv.z + bv.z;
    ov.w = (v.w - mu) * rstd * wv.w + bv.w;
    ((float4*)(out + (size_t)row * DD))[tid] = ov;
}

// ---------------------------------------------------------------------------
extern "C" void kernel_launch(void* const* d_in, const int* in_sizes, int n_in,
                              void* d_out, int out_size)
{
    int mi = -1;
    for (int i = 0; i < n_in; i++)
        if (in_sizes[i] == BB * SS) { mi = i; break; }

    const float *Q, *K, *V, *Wq, *Wk, *Wv, *Wo, *l1w, *l1b, *l2w, *l2b, *lnw, *lnb;
    const unsigned char* mask;
    if (mi == 3) {
        Q   = (const float*)d_in[0];  K   = (const float*)d_in[1];
        V   = (const float*)d_in[2];  mask = (const unsigned char*)d_in[3];
        Wq  = (const float*)d_in[4];  Wk  = (const float*)d_in[5];
        Wv  = (const float*)d_in[6];  Wo  = (const float*)d_in[7];
        l1w = (const float*)d_in[8];  l1b = (const float*)d_in[9];
        l2w = (const float*)d_in[10]; l2b = (const float*)d_in[11];
        lnw = (const float*)d_in[12]; lnb = (const float*)d_in[13];
    } else {
        Q   = (const float*)d_in[0];  K   = (const float*)d_in[1];
        V   = (const float*)d_in[2];
        Wq  = (const float*)d_in[3];  Wk  = (const float*)d_in[4];
        Wv  = (const float*)d_in[5];  Wo  = (const float*)d_in[6];
        l1w = (const float*)d_in[7];  l1b = (const float*)d_in[8];
        l2w = (const float*)d_in[9];  l2b = (const float*)d_in[10];
        lnw = (const float*)d_in[11]; lnb = (const float*)d_in[12];
        mask = (const unsigned char*)d_in[13];
    }

    float *gA, *gB, *gC, *gD;
    cudaGetSymbolAddress((void**)&gA, g_A);
    cudaGetSymbolAddress((void**)&gB, g_B);
    cudaGetSymbolAddress((void**)&gC, g_C);
    cudaGetSymbolAddress((void**)&gD, g_D);

    cudaFuncSetAttribute(mma_gemm<false, false, false>,
                         cudaFuncAttributeMaxDynamicSharedMemorySize, GEMM_SMEM);
    cudaFuncSetAttribute(mma_gemm<true, true, true>,
                         cudaFuncAttributeMaxDynamicSharedMemorySize, GEMM_SMEM);
    cudaFuncSetAttribute(mma_gemm<true, true, false>,
                         cudaFuncAttributeMaxDynamicSharedMemorySize, GEMM_SMEM);

    const dim3 gGrid(DD / 128, MTOK / 128);   // (8, 128)

    // QKV projections (mma.sync split-bf16)
    mma_gemm<false, false, false><<<gGrid, 256, GEMM_SMEM>>>(Q, Wq, nullptr, gA);
    mma_gemm<false, false, false><<<gGrid, 256, GEMM_SMEM>>>(K, Wk, nullptr, gB);
    mma_gemm<false, false, false><<<gGrid, 256, GEMM_SMEM>>>(V, Wv, nullptr, gC);

    // Attention (fp32 CUDA cores)
    const int shmem = 4 * 64 * SMSTRIDE * (int)sizeof(float);
    cudaFuncSetAttribute(attn_kernel, cudaFuncAttributeMaxDynamicSharedMemorySize, shmem);
    attn_kernel<<<dim3(SS / 64, BB * HH), 256, shmem>>>(gA, gB, gC, mask, gD);

    // Output projection
    mma_gemm<false, false, false><<<gGrid, 256, GEMM_SMEM>>>(gD, Wo, nullptr, gA);
    // X = LN(V_att + Q)
    add_ln_kernel<<<MTOK, 256>>>(gA, Q, lnw, lnb, gB);
    // FFN
    mma_gemm<true, true, true ><<<gGrid, 256, GEMM_SMEM>>>(gB, l1w, l1b, gC);
    mma_gemm<true, true, false><<<gGrid, 256, GEMM_SMEM>>>(gC, l2w, l2b, gD);
    // out = LN(ffn + X)
    add_ln_kernel<<<MTOK, 256>>>(gD, gB, lnw, lnb, (float*)d_out);
}

// round 7
// speedup vs baseline: 1.8988x; 1.1572x over previous
#include <cuda_runtime.h>
#include <cuda_bf16.h>
#include <math.h>
#include <stdint.h>

// Problem constants
#define BB 16
#define SS 1024
#define DD 1024
#define HH 16
#define DK 64
#define MTOK (BB*SS)          // 16384 token rows

// Scratch buffers (device globals — no allocation allowed)
__device__ float g_A[(size_t)MTOK * DD];
__device__ float g_B[(size_t)MTOK * DD];
__device__ float g_C[(size_t)MTOK * DD];
__device__ float g_D[(size_t)MTOK * DD];

// ===========================================================================
// Baseline-PTX tensor core helpers (plain sm_103 target: no 'a' features)
// ===========================================================================
__device__ __forceinline__ uint32_t smem_u32(const void* p) {
    uint32_t a;
    asm("{ .reg .u64 t; cvta.to.shared.u64 t, %1; cvt.u32.u64 %0, t; }" : "=r"(a) : "l"(p));
    return a;
}

#define LDSM_X4(R0, R1, R2, R3, addr)                                          \
    asm volatile("ldmatrix.sync.aligned.m8n8.x4.shared.b16 {%0,%1,%2,%3}, [%4];" \
        : "=r"(R0), "=r"(R1), "=r"(R2), "=r"(R3) : "r"(addr))

__device__ __forceinline__ void mma16816(float* d, const uint32_t* a, const uint32_t* b) {
    asm volatile(
        "mma.sync.aligned.m16n8k16.row.col.f32.bf16.bf16.f32 "
        "{%0,%1,%2,%3}, {%4,%5,%6,%7}, {%8,%9}, {%0,%1,%2,%3};"
        : "+f"(d[0]), "+f"(d[1]), "+f"(d[2]), "+f"(d[3])
        : "r"(a[0]), "r"(a[1]), "r"(a[2]), "r"(a[3]), "r"(b[0]), "r"(b[1]));
}

// bf16 split: hi+lo decomposition packed along k (lower 16 bits = first k)
__device__ __forceinline__ void split2(float a, float b, uint32_t& hi, uint32_t& lo) {
    __nv_bfloat16 ah = __float2bfloat16_rn(a);
    __nv_bfloat16 bh = __float2bfloat16_rn(b);
    __nv_bfloat16 al = __float2bfloat16_rn(a - __bfloat162float(ah));
    __nv_bfloat16 bl = __float2bfloat16_rn(b - __bfloat162float(bh));
    hi = (uint32_t)__bfloat16_as_ushort(ah) | ((uint32_t)__bfloat16_as_ushort(bh) << 16);
    lo = (uint32_t)__bfloat16_as_ushort(al) | ((uint32_t)__bfloat16_as_ushort(bl) << 16);
}

// ===========================================================================
// Split-bf16 mma.sync GEMM (unchanged from R6 — verified)
// ===========================================================================
#define RSTRIDE 80
#define T_BYTES (128 * RSTRIDE)
#define STG_BYTES (4 * T_BYTES)
#define GEMM_SMEM (2 * STG_BYTES)
#define NCHUNK (DD / 32)

template<bool TRANSB, bool BIAS, bool RELU>
__global__ void __launch_bounds__(256, 1) mma_gemm(
    const float* __restrict__ A, const float* __restrict__ Bm,
    const float* __restrict__ bias, float* __restrict__ C)
{
    extern __shared__ char smem[];
    const uint32_t sbase = smem_u32(smem);
    const int tid  = threadIdx.x;
    const int lane = tid & 31;
    const int wid  = tid >> 5;
    const int wm   = wid & 3;
    const int wn   = wid >> 2;
    const int n0   = blockIdx.x * 128;
    const int m0   = blockIdx.y * 128;

    float acc[2][8][4] = {};
    float4 rA[4], rB[4];

    auto ldA = [&](int k0) {
        #pragma unroll
        for (int i = 0; i < 4; i++) {
            const int t = tid + 256 * i;
            const int row = t >> 3, kg = t & 7;
            rA[i] = *(const float4*)(A + (size_t)(m0 + row) * DD + k0 + kg * 4);
        }
    };
    auto ldB = [&](int k0) {
        if (TRANSB) {
            #pragma unroll
            for (int i = 0; i < 4; i++) {
                const int t = tid + 256 * i;
                const int row = t >> 3, kg = t & 7;
                rB[i] = *(const float4*)(Bm + (size_t)(n0 + row) * DD + k0 + kg * 4);
            }
        } else {
            #pragma unroll
            for (int i = 0; i < 2; i++) {
                const int t = tid + 256 * i;
                const int kp = t >> 5, ng = t & 31;
                rB[2*i]   = *(const float4*)(Bm + (size_t)(k0 + 2*kp)     * DD + n0 + ng * 4);
                rB[2*i+1] = *(const float4*)(Bm + (size_t)(k0 + 2*kp + 1) * DD + n0 + ng * 4);
            }
        }
    };
    auto stA = [&](char* stg) {
        char* hi = stg;
        char* lo = stg + T_BYTES;
        #pragma unroll
        for (int i = 0; i < 4; i++) {
            const int t = tid + 256 * i;
            const int row = t >> 3, kg = t & 7;
            uint32_t h0, l0, h1, l1;
            split2(rA[i].x, rA[i].y, h0, l0);
            split2(rA[i].z, rA[i].w, h1, l1);
            const int b = row * RSTRIDE + kg * 8;
            *(uint32_t*)(hi + b)     = h0;  *(uint32_t*)(hi + b + 4) = h1;
            *(uint32_t*)(lo + b)     = l0;  *(uint32_t*)(lo + b + 4) = l1;
        }
    };
    auto stB = [&](char* stg) {
        char* hi = stg + 2 * T_BYTES;
        char* lo = stg + 3 * T_BYTES;
        if (TRANSB) {
            #pragma unroll
            for (int i = 0; i < 4; i++) {
                const int t = tid + 256 * i;
                const int row = t >> 3, kg = t & 7;
                uint32_t h0, l0, h1, l1;
                split2(rB[i].x, rB[i].y, h0, l0);
                split2(rB[i].z, rB[i].w, h1, l1);
                const int b = row * RSTRIDE + kg * 8;
                *(uint32_t*)(hi + b)     = h0;  *(uint32_t*)(hi + b + 4) = h1;
                *(uint32_t*)(lo + b)     = l0;  *(uint32_t*)(lo + b + 4) = l1;
            }
        } else {
            #pragma unroll
            for (int i = 0; i < 2; i++) {
                const int t = tid + 256 * i;
                const int kp = t >> 5, ng = t & 31;
                const float v0[4] = {rB[2*i].x, rB[2*i].y, rB[2*i].z, rB[2*i].w};
                const float v1[4] = {rB[2*i+1].x, rB[2*i+1].y, rB[2*i+1].z, rB[2*i+1].w};
                #pragma unroll
                for (int j = 0; j < 4; j++) {
                    uint32_t h, l;
                    split2(v0[j], v1[j], h, l);
                    const int n = ng * 4 + j;
                    const int b = n * RSTRIDE + kp * 4;
                    *(uint32_t*)(hi + b) = h;
                    *(uint32_t*)(lo + b) = l;
                }
            }
        }
    };
    auto compute = [&](uint32_t stg) {
        const uint32_t sAh = stg;
        const uint32_t sAl = stg + T_BYTES;
        const uint32_t sBh = stg + 2 * T_BYTES;
        const uint32_t sBl = stg + 3 * T_BYTES;
        #pragma unroll
        for (int ks = 0; ks < 2; ks++) {
            const int kb = ks * 16 * 2;
            uint32_t ah[2][4], al[2][4], bh[4][4], bl[4][4];
            const int arow = (lane & 15);
            const int acb  = kb + ((lane >> 4) * 8) * 2;
            #pragma unroll
            for (int mt = 0; mt < 2; mt++) {
                const uint32_t off = (uint32_t)((wm * 32 + mt * 16 + arow) * RSTRIDE + acb);
                LDSM_X4(ah[mt][0], ah[mt][1], ah[mt][2], ah[mt][3], sAh + off);
                LDSM_X4(al[mt][0], al[mt][1], al[mt][2], al[mt][3], sAl + off);
            }
            const int q  = lane >> 3;
            const int lr = lane & 7;
            const int brow_q = ((q & 2) ? 8 : 0) + lr;
            const int bcb    = kb + ((q & 1) * 8) * 2;
            #pragma unroll
            for (int p = 0; p < 4; p++) {
                const uint32_t off = (uint32_t)((wn * 64 + p * 16 + brow_q) * RSTRIDE + bcb);
                LDSM_X4(bh[p][0], bh[p][1], bh[p][2], bh[p][3], sBh + off);
                LDSM_X4(bl[p][0], bl[p][1], bl[p][2], bl[p][3], sBl + off);
            }
            #pragma unroll
            for (int mt = 0; mt < 2; mt++)
                #pragma unroll
                for (int p = 0; p < 4; p++)
                    #pragma unroll
                    for (int h = 0; h < 2; h++) {
                        float* d = acc[mt][p * 2 + h];
                        mma16816(d, ah[mt], &bh[p][h * 2]);
                        mma16816(d, ah[mt], &bl[p][h * 2]);
                        mma16816(d, al[mt], &bh[p][h * 2]);
                    }
        }
    };

    ldA(0); ldB(0);
    stA(smem); stB(smem);
    __syncthreads();
    for (int c = 0; c < NCHUNK; c++) {
        const int s = c & 1;
        if (c + 1 < NCHUNK) { ldA((c + 1) * 32); ldB((c + 1) * 32); }
        compute(sbase + s * STG_BYTES);
        if (c + 1 < NCHUNK) { stA(smem + (s ^ 1) * STG_BYTES); stB(smem + (s ^ 1) * STG_BYTES); }
        __syncthreads();
    }

    #pragma unroll
    for (int mt = 0; mt < 2; mt++) {
        const int row = m0 + wm * 32 + mt * 16 + (lane >> 2);
        #pragma unroll
        for (int nt = 0; nt < 8; nt++) {
            const int col = n0 + wn * 64 + nt * 8 + (lane & 3) * 2;
            float b0 = 0.f, b1 = 0.f;
            if (BIAS) { b0 = __ldg(bias + col); b1 = __ldg(bias + col + 1); }
            float2 v01, v23;
            v01.x = acc[mt][nt][0] + b0;  v01.y = acc[mt][nt][1] + b1;
            v23.x = acc[mt][nt][2] + b0;  v23.y = acc[mt][nt][3] + b1;
            if (RELU) {
                v01.x = fmaxf(v01.x, 0.f); v01.y = fmaxf(v01.y, 0.f);
                v23.x = fmaxf(v23.x, 0.f); v23.y = fmaxf(v23.y, 0.f);
            }
            *(float2*)(C + (size_t)row * DD + col)       = v01;
            *(float2*)(C + (size_t)(row + 8) * DD + col) = v23;
        }
    }
}

// ===========================================================================
// Tensor-core flash attention: split-bf16 mma.sync for QK^T and PV.
// CTA = (qt, b*h), 128 threads / 4 warps, q-tile 64, k-tile 64, DK=64.
// SMEM tiles stride 72 bf16 (144B) -> conflict-free ldmatrix.
// Warp w computes q rows w*16..w*16+15.
// ===========================================================================
#define AST   72                         // bf16 elems per smem row
#define ATILE (64 * AST * 2)             // 9216 bytes per tile
#define ATT_SMEM (6 * ATILE)             // Qh Ql Kh Kl Vth Vtl = 55296 B

__global__ void __launch_bounds__(128) attn_mma_kernel(
    const float* __restrict__ Qp, const float* __restrict__ Kp,
    const float* __restrict__ Vp, const unsigned char* __restrict__ mask,
    float* __restrict__ ctx)
{
    extern __shared__ char sm[];
    const uint32_t sb = smem_u32(sm);
    const int tid  = threadIdx.x;
    const int lane = tid & 31;
    const int w    = tid >> 5;
    const int qt   = blockIdx.x;           // 0..15
    const int bh   = blockIdx.y;           // 0..255
    const int b    = bh >> 4;
    const int h    = bh & 15;

    char* sQh = sm;
    char* sQl = sm + ATILE;
    char* sKh = sm + 2 * ATILE;
    char* sKl = sm + 3 * ATILE;
    char* sVh = sm + 4 * ATILE;
    char* sVl = sm + 5 * ATILE;

    const size_t base = (size_t)b * SS * DD + (size_t)h * DK;

    // ---- load Q tile (rows q, cols d), split bf16 ----
    {
        const int row  = tid >> 1;
        const int half = tid & 1;
        const float* src = Qp + base + (size_t)(qt * 64 + row) * DD + half * 32;
        #pragma unroll
        for (int j = 0; j < 8; j++) {
            const float4 v = *(const float4*)(src + j * 4);
            uint32_t h0, l0, h1, l1;
            split2(v.x, v.y, h0, l0);
            split2(v.z, v.w, h1, l1);
            const int bo = row * (AST * 2) + (half * 32 + j * 4) * 2;
            *(uint32_t*)(sQh + bo)     = h0;  *(uint32_t*)(sQh + bo + 4) = h1;
            *(uint32_t*)(sQl + bo)     = l0;  *(uint32_t*)(sQl + bo + 4) = l1;
        }
    }

    const int r0 = lane >> 2;              // local row within warp's 16
    unsigned char pm[2];
    pm[0] = mask[(size_t)b * SS + qt * 64 + w * 16 + r0];
    pm[1] = mask[(size_t)b * SS + qt * 64 + w * 16 + r0 + 8];

    float m_r[2] = {-1e30f, -1e30f};
    float l_r[2] = {0.f, 0.f};
    float acc_o[8][4] = {};

    const float NEGV  = -4294967295.0f;
    const float scale = 1.0f / 8.000001f;

    // fragment geometry (identical to verified GEMM)
    const int arow   = lane & 15;
    const int acb    = ((lane >> 4) * 8) * 2;
    const int qq     = lane >> 3;
    const int lr     = lane & 7;
    const int brow_q = ((qq & 2) ? 8 : 0) + lr;
    const int bcb    = ((qq & 1) * 8) * 2;

    for (int kt = 0; kt <= qt; kt++) {
        __syncthreads();   // Q ready (kt=0) / prior compute done with K,V

        // ---- load K tile (rows kseq, cols d), split bf16 ----
        {
            const int row  = tid >> 1;
            const int half = tid & 1;
            const float* src = Kp + base + (size_t)(kt * 64 + row) * DD + half * 32;
            #pragma unroll
            for (int j = 0; j < 8; j++) {
                const float4 v = *(const float4*)(src + j * 4);
                uint32_t h0, l0, h1, l1;
                split2(v.x, v.y, h0, l0);
                split2(v.z, v.w, h1, l1);
                const int bo = row * (AST * 2) + (half * 32 + j * 4) * 2;
                *(uint32_t*)(sKh + bo)     = h0;  *(uint32_t*)(sKh + bo + 4) = h1;
                *(uint32_t*)(sKl + bo)     = l0;  *(uint32_t*)(sKl + bo + 4) = l1;
            }
        }
        // ---- load V tile transposed: Vt[d][seq], split bf16 ----
        {
            const int row  = tid >> 1;     // seq within tile
            const int half = tid & 1;
            const float* src = Vp + base + (size_t)(kt * 64 + row) * DD + half * 32;
            #pragma unroll
            for (int j = 0; j < 8; j++) {
                const float4 v = *(const float4*)(src + j * 4);
                const float vv[4] = {v.x, v.y, v.z, v.w};
                #pragma unroll
                for (int e = 0; e < 4; e++) {
                    const int d = half * 32 + j * 4 + e;
                    __nv_bfloat16 hi = __float2bfloat16_rn(vv[e]);
                    __nv_bfloat16 lo = __float2bfloat16_rn(vv[e] - __bfloat162float(hi));
                    *(__nv_bfloat16*)(sVh + d * (AST * 2) + row * 2) = hi;
                    *(__nv_bfloat16*)(sVl + d * (AST * 2) + row * 2) = lo;
                }
            }
        }
        __syncthreads();

        // ---- scores S = Q @ K^T (split 3-term) ----
        float s[8][4] = {};
        const uint32_t uQh = sb;
        const uint32_t uQl = sb + ATILE;
        const uint32_t uKh = sb + 2 * ATILE;
        const uint32_t uKl = sb + 3 * ATILE;
        #pragma unroll
        for (int ks = 0; ks < 4; ks++) {
            const int kb = ks * 32;
            uint32_t ah[4], al[4], kh[4][4], kl[4][4];
            {
                const uint32_t off = (uint32_t)((w * 16 + arow) * (AST * 2) + kb + acb);
                LDSM_X4(ah[0], ah[1], ah[2], ah[3], uQh + off);
                LDSM_X4(al[0], al[1], al[2], al[3], uQl + off);
            }
            #pragma unroll
            for (int p = 0; p < 4; p++) {
                const uint32_t off = (uint32_t)((p * 16 + brow_q) * (AST * 2) + kb + bcb);
                LDSM_X4(kh[p][0], kh[p][1], kh[p][2], kh[p][3], uKh + off);
                LDSM_X4(kl[p][0], kl[p][1], kl[p][2], kl[p][3], uKl + off);
            }
            #pragma unroll
            for (int p = 0; p < 4; p++)
                #pragma unroll
                for (int hh = 0; hh < 2; hh++) {
                    float* d = s[p * 2 + hh];
                    mma16816(d, ah, &kh[p][hh * 2]);
                    mma16816(d, ah, &kl[p][hh * 2]);
                    mma16816(d, al, &kh[p][hh * 2]);
                }
        }

        // ---- scale + causal/pad mask ----
        const int qg0 = qt * 64 + w * 16 + r0;
        #pragma unroll
        for (int nt = 0; nt < 8; nt++) {
            const int cg = kt * 64 + nt * 8 + (lane & 3) * 2;
            #pragma unroll
            for (int j = 0; j < 4; j++) {
                const int row_g = (j >> 1) ? qg0 + 8 : qg0;
                const int col_g = cg + (j & 1);
                s[nt][j] *= scale;
                if (col_g > row_g || pm[j >> 1]) s[nt][j] = NEGV;
            }
        }

        // ---- online softmax (per row-half, reduced across lane quad) ----
        #pragma unroll
        for (int half = 0; half < 2; half++) {
            float tm = -1e30f;
            #pragma unroll
            for (int nt = 0; nt < 8; nt++)
                tm = fmaxf(tm, fmaxf(s[nt][half * 2], s[nt][half * 2 + 1]));
            tm = fmaxf(tm, __shfl_xor_sync(0xffffffffu, tm, 1));
            tm = fmaxf(tm, __shfl_xor_sync(0xffffffffu, tm, 2));
            const float mn = fmaxf(m_r[half], tm);
            const float f = __expf(m_r[half] - mn);
            float ps = 0.f;
            #pragma unroll
            for (int nt = 0; nt < 8; nt++) {
                const float p0 = __expf(s[nt][half * 2]     - mn);
                const float p1 = __expf(s[nt][half * 2 + 1] - mn);
                s[nt][half * 2]     = p0;
                s[nt][half * 2 + 1] = p1;
                ps += p0 + p1;
                acc_o[nt][half * 2]     *= f;
                acc_o[nt][half * 2 + 1] *= f;
            }
            ps += __shfl_xor_sync(0xffffffffu, ps, 1);
            ps += __shfl_xor_sync(0xffffffffu, ps, 2);
            l_r[half] = l_r[half] * f + ps;
            m_r[half] = mn;
        }

        // ---- O += P @ V (P from registers, split 3-term) ----
        const uint32_t uVh = sb + 4 * ATILE;
        const uint32_t uVl = sb + 5 * ATILE;
        #pragma unroll
        for (int ks = 0; ks < 4; ks++) {
            uint32_t ph[4], pl[4];
            const int t0 = 2 * ks, t1 = 2 * ks + 1;
            split2(s[t0][0], s[t0][1], ph[0], pl[0]);
            split2(s[t0][2], s[t0][3], ph[1], pl[1]);
            split2(s[t1][0], s[t1][1], ph[2], pl[2]);
            split2(s[t1][2], s[t1][3], ph[3], pl[3]);

            const int kb = ks * 32;
            uint32_t vh[4][4], vl[4][4];
            #pragma unroll
            for (int p = 0; p < 4; p++) {
                const uint32_t off = (uint32_t)((p * 16 + brow_q) * (AST * 2) + kb + bcb);
                LDSM_X4(vh[p][0], vh[p][1], vh[p][2], vh[p][3], uVh + off);
                LDSM_X4(vl[p][0], vl[p][1], vl[p][2], vl[p][3], uVl + off);
            }
            #pragma unroll
            for (int p = 0; p < 4; p++)
                #pragma unroll
                for (int hh = 0; hh < 2; hh++) {
                    float* d = acc_o[p * 2 + hh];
                    mma16816(d, ph, &vh[p][hh * 2]);
                    mma16816(d, ph, &vl[p][hh * 2]);
                    mma16816(d, pl, &vh[p][hh * 2]);
                }
        }
    }

    // ---- normalize + write ctx ----
    const float inv0 = 1.0f / l_r[0];
    const float inv1 = 1.0f / l_r[1];
    const int row0 = qt * 64 + w * 16 + r0;
    #pragma unroll
    for (int nt = 0; nt < 8; nt++) {
        const int col = h * DK + nt * 8 + (lane & 3) * 2;
        float2 v0, v1;
        v0.x = acc_o[nt][0] * inv0;  v0.y = acc_o[nt][1] * inv0;
        v1.x = acc_o[nt][2] * inv1;  v1.y = acc_o[nt][3] * inv1;
        *(float2*)(ctx + ((size_t)b * SS + row0)     * DD + col) = v0;
        *(float2*)(ctx + ((size_t)b * SS + row0 + 8) * DD + col) = v1;
    }
}

// ---------------------------------------------------------------------------
// out[row] = LayerNorm(X[row] + R[row]) * w + b
// ---------------------------------------------------------------------------
__global__ void __launch_bounds__(256) add_ln_kernel(
    const float* __restrict__ X, const float* __restrict__ R,
    const float* __restrict__ w, const float* __restrict__ bb,
    float* __restrict__ out)
{
    const int row = blockIdx.x;
    const int tid = threadIdx.x;
    const float4* x4 = (const float4*)(X + (size_t)row * DD);
    const float4* r4 = (const float4*)(R + (size_t)row * DD);
    float4 v = x4[tid];
    const float4 r = r4[tid];
    v.x += r.x; v.y += r.y; v.z += r.z; v.w += r.w;

    float sum = v.x + v.y + v.z + v.w;
    float sq  = v.x*v.x + v.y*v.y + v.z*v.z + v.w*v.w;
    #pragma unroll
    for (int off = 16; off; off >>= 1) {
        sum += __shfl_xor_sync(0xffffffffu, sum, off);
        sq  += __shfl_xor_sync(0xffffffffu, sq, off);
    }
    __shared__ float ssum[8], ssq[8];
    if ((tid & 31) == 0) { ssum[tid >> 5] = sum; ssq[tid >> 5] = sq; }
    __syncthreads();
    float tot = 0.f, totq = 0.f;
    #pragma unroll
    for (int i = 0; i < 8; i++) { tot += ssum[i]; totq += ssq[i]; }
    const float mu   = tot * (1.0f / DD);
    const float var  = totq * (1.0f / DD) - mu * mu;
    const float rstd = rsqrtf(var + 1e-5f);

    const float4 wv = ((const float4*)w)[tid];
    const float4 bv = ((const float4*)bb)[tid];
    float4 ov;
    ov.x = (v.x - mu) * rstd * wv.x + bv.x;
    ov.y = (v.y - mu) * rstd * wv.y + bv.y;
    ov.z = (v.z - mu) * rstd * wv.z + bv.z;
    ov.w = (v.w - mu) * rstd * wv.w + bv.w;
    ((float4*)(out + (size_t)row * DD))[tid] = ov;
}

// ---------------------------------------------------------------------------
extern "C" void kernel_launch(void* const* d_in, const int* in_sizes, int n_in,
                              void* d_out, int out_size)
{
    int mi = -1;
    for (int i = 0; i < n_in; i++)
        if (in_sizes[i] == BB * SS) { mi = i; break; }

    const float *Q, *K, *V, *Wq, *Wk, *Wv, *Wo, *l1w, *l1b, *l2w, *l2b, *lnw, *lnb;
    const unsigned char* mask;
    if (mi == 3) {
        Q   = (const float*)d_in[0];  K   = (const float*)d_in[1];
        V   = (const float*)d_in[2];  mask = (const unsigned char*)d_in[3];
        Wq  = (const float*)d_in[4];  Wk  = (const float*)d_in[5];
        Wv  = (const float*)d_in[6];  Wo  = (const float*)d_in[7];
        l1w = (const float*)d_in[8];  l1b = (const float*)d_in[9];
        l2w = (const float*)d_in[10]; l2b = (const float*)d_in[11];
        lnw = (const float*)d_in[12]; lnb = (const float*)d_in[13];
    } else {
        Q   = (const float*)d_in[0];  K   = (const float*)d_in[1];
        V   = (const float*)d_in[2];
        Wq  = (const float*)d_in[3];  Wk  = (const float*)d_in[4];
        Wv  = (const float*)d_in[5];  Wo  = (const float*)d_in[6];
        l1w = (const float*)d_in[7];  l1b = (const float*)d_in[8];
        l2w = (const float*)d_in[9];  l2b = (const float*)d_in[10];
        lnw = (const float*)d_in[11]; lnb = (const float*)d_in[12];
        mask = (const unsigned char*)d_in[13];
    }

    float *gA, *gB, *gC, *gD;
    cudaGetSymbolAddress((void**)&gA, g_A);
    cudaGetSymbolAddress((void**)&gB, g_B);
    cudaGetSymbolAddress((void**)&gC, g_C);
    cudaGetSymbolAddress((void**)&gD, g_D);

    cudaFuncSetAttribute(mma_gemm<false, false, false>,
                         cudaFuncAttributeMaxDynamicSharedMemorySize, GEMM_SMEM);
    cudaFuncSetAttribute(mma_gemm<true, true, true>,
                         cudaFuncAttributeMaxDynamicSharedMemorySize, GEMM_SMEM);
    cudaFuncSetAttribute(mma_gemm<true, true, false>,
                         cudaFuncAttributeMaxDynamicSharedMemorySize, GEMM_SMEM);
    cudaFuncSetAttribute(attn_mma_kernel,
                         cudaFuncAttributeMaxDynamicSharedMemorySize, ATT_SMEM);

    const dim3 gGrid(DD / 128, MTOK / 128);   // (8, 128)

    // QKV projections (mma.sync split-bf16)
    mma_gemm<false, false, false><<<gGrid, 256, GEMM_SMEM>>>(Q, Wq, nullptr, gA);
    mma_gemm<false, false, false><<<gGrid, 256, GEMM_SMEM>>>(K, Wk, nullptr, gB);
    mma_gemm<false, false, false><<<gGrid, 256, GEMM_SMEM>>>(V, Wv, nullptr, gC);

    // Attention (mma.sync split-bf16 flash)
    attn_mma_kernel<<<dim3(SS / 64, BB * HH), 128, ATT_SMEM>>>(gA, gB, gC, mask, gD);

    // Output projection
    mma_gemm<false, false, false><<<gGrid, 256, GEMM_SMEM>>>(gD, Wo, nullptr, gA);
    // X = LN(V_att + Q)
    add_ln_kernel<<<MTOK, 256>>>(gA, Q, lnw, lnb, gB);
    // FFN
    mma_gemm<true, true, true ><<<gGrid, 256, GEMM_SMEM>>>(gB, l1w, l1b, gC);
    mma_gemm<true, true, false><<<gGrid, 256, GEMM_SMEM>>>(gC, l2w, l2b, gD);
    // out = LN(ffn + X)
    add_ln_kernel<<<MTOK, 256>>>(gD, gB, lnw, lnb, (float*)d_out);
}

// round 8
// speedup vs baseline: 2.4413x; 1.2858x over previous
#include <cuda_runtime.h>
#include <cuda_bf16.h>
#include <stdint.h>

// Problem constants
#define BB 16
#define SS 1024
#define DD 1024
#define HH 16
#define DK 64
#define MTOK (BB*SS)          // 16384 token rows

// Scratch buffers (device globals — no allocation allowed)
__device__ float g_A[(size_t)MTOK * DD];
__device__ float g_B[(size_t)MTOK * DD];
__device__ float g_C[(size_t)MTOK * DD];
// 4 pairs of split-bf16 activation buffers (hi/lo), each MTOK*DD
__device__ __nv_bfloat16 g_bf[(size_t)4 * 2 * MTOK * DD];
// 6 weight pairs (hi/lo), each DD*DD, all stored [N,K]
__device__ __nv_bfloat16 g_w[(size_t)6 * 2 * DD * DD];

// ===========================================================================
// Helpers
// ===========================================================================
__device__ __forceinline__ uint32_t smem_u32(const void* p) {
    uint32_t a;
    asm("{ .reg .u64 t; cvta.to.shared.u64 t, %1; cvt.u32.u64 %0, t; }" : "=r"(a) : "l"(p));
    return a;
}

#define LDSM_X4(R0, R1, R2, R3, addr)                                          \
    asm volatile("ldmatrix.sync.aligned.m8n8.x4.shared.b16 {%0,%1,%2,%3}, [%4];" \
        : "=r"(R0), "=r"(R1), "=r"(R2), "=r"(R3) : "r"(addr))

__device__ __forceinline__ void mma16816(float* d, const uint32_t* a, const uint32_t* b) {
    asm volatile(
        "mma.sync.aligned.m16n8k16.row.col.f32.bf16.bf16.f32 "
        "{%0,%1,%2,%3}, {%4,%5,%6,%7}, {%8,%9}, {%0,%1,%2,%3};"
        : "+f"(d[0]), "+f"(d[1]), "+f"(d[2]), "+f"(d[3])
        : "r"(a[0]), "r"(a[1]), "r"(a[2]), "r"(a[3]), "r"(b[0]), "r"(b[1]));
}

__device__ __forceinline__ void split2(float a, float b, uint32_t& hi, uint32_t& lo) {
    __nv_bfloat16 ah = __float2bfloat16_rn(a);
    __nv_bfloat16 bh = __float2bfloat16_rn(b);
    __nv_bfloat16 al = __float2bfloat16_rn(a - __bfloat162float(ah));
    __nv_bfloat16 bl = __float2bfloat16_rn(b - __bfloat162float(bh));
    hi = (uint32_t)__bfloat16_as_ushort(ah) | ((uint32_t)__bfloat16_as_ushort(bh) << 16);
    lo = (uint32_t)__bfloat16_as_ushort(al) | ((uint32_t)__bfloat16_as_ushort(bl) << 16);
}

#define CP16(sm, gm) asm volatile("cp.async.cg.shared.global [%0], [%1], 16;" :: "r"(sm), "l"(gm))
#define CP_COMMIT()  asm volatile("cp.async.commit_group;")
#define CP_WAIT0()   asm volatile("cp.async.wait_group 0;" ::: "memory")

// ===========================================================================
// Convert kernels (one-time per launch)
// ===========================================================================
// fp32 -> split bf16, same layout (4 elems / thread)
__global__ void conv_a(const float* __restrict__ X,
                       __nv_bfloat16* __restrict__ Xh, __nv_bfloat16* __restrict__ Xl)
{
    const size_t i = ((size_t)blockIdx.x * 256 + threadIdx.x) * 4;
    const float4 v = *(const float4*)(X + i);
    uint32_t h0, l0, h1, l1;
    split2(v.x, v.y, h0, l0);
    split2(v.z, v.w, h1, l1);
    *(uint32_t*)(Xh + i)     = h0;  *(uint32_t*)(Xh + i + 2) = h1;
    *(uint32_t*)(Xl + i)     = l0;  *(uint32_t*)(Xl + i + 2) = l1;
}

// W [K,N] fp32 -> Wh/Wl [N,K] bf16 (transpose via smem)
__global__ void conv_w_t(const float* __restrict__ W,
                         __nv_bfloat16* __restrict__ Wh, __nv_bfloat16* __restrict__ Wl)
{
    __shared__ float t[32][33];
    const int n0 = blockIdx.x * 32;
    const int k0 = blockIdx.y * 32;
    const int tx = threadIdx.x, ty = threadIdx.y;
    #pragma unroll
    for (int j = ty; j < 32; j += 8)
        t[j][tx] = W[(size_t)(k0 + j) * DD + n0 + tx];
    __syncthreads();
    const int k = k0 + tx;
    #pragma unroll
    for (int j = ty; j < 32; j += 8) {
        const float v = t[tx][j];               // = W[k][n0+j]
        const __nv_bfloat16 hi = __float2bfloat16_rn(v);
        const __nv_bfloat16 lo = __float2bfloat16_rn(v - __bfloat162float(hi));
        Wh[(size_t)(n0 + j) * DD + k] = hi;
        Wl[(size_t)(n0 + j) * DD + k] = lo;
    }
}

// ===========================================================================
// Split-bf16 mma.sync GEMM: C = A[M,K] @ B^T, B pre-split [N,K] bf16.
// A pre-split [M,K] bf16. CTA 128x128, BK=32, cp.async double-buffered.
// ===========================================================================
#define RSTRIDE 80
#define T_BYTES (128 * RSTRIDE)
#define STG_BYTES (4 * T_BYTES)
#define GEMM_SMEM (2 * STG_BYTES)
#define NCHUNK (DD / 32)

template<bool BIAS, bool RELU, bool OUTF32, bool OUTSPLIT>
__global__ void __launch_bounds__(256, 1) mma_gemm(
    const __nv_bfloat16* __restrict__ Ah, const __nv_bfloat16* __restrict__ Al,
    const __nv_bfloat16* __restrict__ Bh, const __nv_bfloat16* __restrict__ Bl,
    const float* __restrict__ bias,
    float* __restrict__ Cf,
    __nv_bfloat16* __restrict__ Ch, __nv_bfloat16* __restrict__ Cl)
{
    extern __shared__ char smem[];
    const uint32_t sbase = smem_u32(smem);
    const int tid  = threadIdx.x;
    const int lane = tid & 31;
    const int wid  = tid >> 5;
    const int wm   = wid & 3;
    const int wn   = wid >> 2;
    const int n0   = blockIdx.x * 128;
    const int m0   = blockIdx.y * 128;

    float acc[2][8][4] = {};

    auto issue = [&](int c, int s) {
        const int k0 = c * 32;
        const uint32_t st = sbase + s * STG_BYTES;
        #pragma unroll
        for (int i = 0; i < 8; i++) {
            const int id   = tid + 256 * i;
            const int tile = id >> 9;                  // 0:Ah 1:Al 2:Bh 3:Bl
            const int r    = (id >> 2) & 127;
            const int seg  = id & 3;
            const __nv_bfloat16* g =
                (tile == 0 ? Ah : tile == 1 ? Al : tile == 2 ? Bh : Bl)
                + (size_t)((tile < 2 ? m0 : n0) + r) * DD + k0 + seg * 8;
            CP16(st + tile * T_BYTES + r * RSTRIDE + seg * 16, g);
        }
    };

    auto compute = [&](uint32_t stg) {
        const uint32_t sAh = stg;
        const uint32_t sAl = stg + T_BYTES;
        const uint32_t sBh = stg + 2 * T_BYTES;
        const uint32_t sBl = stg + 3 * T_BYTES;
        #pragma unroll
        for (int ks = 0; ks < 2; ks++) {
            const int kb = ks * 16 * 2;
            uint32_t ah[2][4], al[2][4], bh[4][4], bl[4][4];
            const int arow = (lane & 15);
            const int acb  = kb + ((lane >> 4) * 8) * 2;
            #pragma unroll
            for (int mt = 0; mt < 2; mt++) {
                const uint32_t off = (uint32_t)((wm * 32 + mt * 16 + arow) * RSTRIDE + acb);
                LDSM_X4(ah[mt][0], ah[mt][1], ah[mt][2], ah[mt][3], sAh + off);
                LDSM_X4(al[mt][0], al[mt][1], al[mt][2], al[mt][3], sAl + off);
            }
            const int q  = lane >> 3;
            const int lr = lane & 7;
            const int brow_q = ((q & 2) ? 8 : 0) + lr;
            const int bcb    = kb + ((q & 1) * 8) * 2;
            #pragma unroll
            for (int p = 0; p < 4; p++) {
                const uint32_t off = (uint32_t)((wn * 64 + p * 16 + brow_q) * RSTRIDE + bcb);
                LDSM_X4(bh[p][0], bh[p][1], bh[p][2], bh[p][3], sBh + off);
                LDSM_X4(bl[p][0], bl[p][1], bl[p][2], bl[p][3], sBl + off);
            }
            #pragma unroll
            for (int mt = 0; mt < 2; mt++)
                #pragma unroll
                for (int p = 0; p < 4; p++)
                    #pragma unroll
                    for (int h = 0; h < 2; h++) {
                        float* d = acc[mt][p * 2 + h];
                        mma16816(d, ah[mt], &bh[p][h * 2]);
                        mma16816(d, ah[mt], &bl[p][h * 2]);
                        mma16816(d, al[mt], &bh[p][h * 2]);
                    }
        }
    };

    issue(0, 0); CP_COMMIT();
    for (int c = 0; c < NCHUNK; c++) {
        const int s = c & 1;
        CP_WAIT0();
        __syncthreads();
        if (c + 1 < NCHUNK) { issue(c + 1, s ^ 1); CP_COMMIT(); }
        compute(sbase + s * STG_BYTES);
    }

    // Epilogue
    #pragma unroll
    for (int mt = 0; mt < 2; mt++) {
        const int row = m0 + wm * 32 + mt * 16 + (lane >> 2);
        #pragma unroll
        for (int nt = 0; nt < 8; nt++) {
            const int col = n0 + wn * 64 + nt * 8 + (lane & 3) * 2;
            float b0 = 0.f, b1 = 0.f;
            if (BIAS) { b0 = __ldg(bias + col); b1 = __ldg(bias + col + 1); }
            float2 v01, v23;
            v01.x = acc[mt][nt][0] + b0;  v01.y = acc[mt][nt][1] + b1;
            v23.x = acc[mt][nt][2] + b0;  v23.y = acc[mt][nt][3] + b1;
            if (RELU) {
                v01.x = fmaxf(v01.x, 0.f); v01.y = fmaxf(v01.y, 0.f);
                v23.x = fmaxf(v23.x, 0.f); v23.y = fmaxf(v23.y, 0.f);
            }
            if (OUTF32) {
                *(float2*)(Cf + (size_t)row * DD + col)       = v01;
                *(float2*)(Cf + (size_t)(row + 8) * DD + col) = v23;
            }
            if (OUTSPLIT) {
                uint32_t h, l;
                split2(v01.x, v01.y, h, l);
                *(uint32_t*)(Ch + (size_t)row * DD + col) = h;
                *(uint32_t*)(Cl + (size_t)row * DD + col) = l;
                split2(v23.x, v23.y, h, l);
                *(uint32_t*)(Ch + (size_t)(row + 8) * DD + col) = h;
                *(uint32_t*)(Cl + (size_t)(row + 8) * DD + col) = l;
            }
        }
    }
}

// ===========================================================================
// Tensor-core flash attention on pre-split bf16 inputs.
// CTA = (qt of 128 rows, b*h), 256 threads / 8 warps; k-tile 64, DK=64.
// Writes split-bf16 ctx directly.
// ===========================================================================
#define AST 72                             // bf16 elems per smem row (144 B)
#define QTILE_B (128 * AST * 2)            // 18432
#define KTILE_B (64 * AST * 2)             // 9216
#define ATT_SMEM (2 * QTILE_B + 4 * KTILE_B)   // 73728

__global__ void __launch_bounds__(256) attn_mma_kernel(
    const __nv_bfloat16* __restrict__ Qh_, const __nv_bfloat16* __restrict__ Ql_,
    const __nv_bfloat16* __restrict__ Kh_, const __nv_bfloat16* __restrict__ Kl_,
    const __nv_bfloat16* __restrict__ Vh_, const __nv_bfloat16* __restrict__ Vl_,
    const unsigned char* __restrict__ mask,
    __nv_bfloat16* __restrict__ Ch, __nv_bfloat16* __restrict__ Cl)
{
    extern __shared__ char sm[];
    const uint32_t sb = smem_u32(sm);
    const int tid  = threadIdx.x;
    const int lane = tid & 31;
    const int w    = tid >> 5;             // 0..7
    const int qt   = blockIdx.x;           // 0..7 (128-row q blocks)
    const int bh   = blockIdx.y;
    const int b    = bh >> 4;
    const int h    = bh & 15;

    const uint32_t uQh = sb;
    const uint32_t uQl = sb + QTILE_B;
    const uint32_t uKh = sb + 2 * QTILE_B;
    const uint32_t uKl = uKh + KTILE_B;
    const uint32_t uVh = uKh + 2 * KTILE_B;
    const uint32_t uVl = uKh + 3 * KTILE_B;

    const size_t base = (size_t)b * SS * DD + (size_t)h * DK;

    // ---- Q tile: 128 rows x 64 bf16, hi+lo via cp.async ----
    {
        #pragma unroll
        for (int i = 0; i < 8; i++) {
            const int id   = tid + 256 * i;       // 0..2047
            const int tile = id >> 10;            // 0 hi, 1 lo
            const int r    = (id >> 3) & 127;
            const int seg  = id & 7;
            const __nv_bfloat16* g = (tile ? Ql_ : Qh_)
                + base + (size_t)(qt * 128 + r) * DD + seg * 8;
            CP16(sb + tile * QTILE_B + r * 144 + seg * 16, g);
        }
        CP_COMMIT();
    }

    const int r0 = lane >> 2;
    unsigned char pm[2];
    pm[0] = mask[(size_t)b * SS + qt * 128 + w * 16 + r0];
    pm[1] = mask[(size_t)b * SS + qt * 128 + w * 16 + r0 + 8];

    float m_r[2] = {-1e30f, -1e30f};
    float l_r[2] = {0.f, 0.f};
    float acc_o[8][4] = {};

    const float NEGV  = -4294967295.0f;
    const float scale = 1.0f / 8.000001f;

    // fragment geometry (verified)
    const int arow   = lane & 15;
    const int acb    = ((lane >> 4) * 8) * 2;
    const int qq     = lane >> 3;
    const int lr     = lane & 7;
    const int brow_q = ((qq & 2) ? 8 : 0) + lr;
    const int bcb    = ((qq & 1) * 8) * 2;

    const int kmax = 2 * qt + 1;
    for (int kt = 0; kt <= kmax; kt++) {
        __syncthreads();   // prior compute done with K/V smem

        // K tile: 64 rows x 64 bf16, hi+lo via cp.async (4 chunks/thread)
        #pragma unroll
        for (int i = 0; i < 4; i++) {
            const int id   = tid + 256 * i;       // 0..1023
            const int tile = id >> 9;             // 0 hi, 1 lo
            const int r    = (id >> 3) & 63;
            const int seg  = id & 7;
            const __nv_bfloat16* g = (tile ? Kl_ : Kh_)
                + base + (size_t)(kt * 64 + r) * DD + seg * 8;
            CP16(uKh + tile * KTILE_B + r * 144 + seg * 16, g);
        }
        CP_COMMIT();

        // V tile transposed: Vt[d][seq]. Thread: 2 seq rows x 8 d.
        {
            const int rv   = (tid & 31) * 2;      // seq pair
            const int dblk = tid >> 5;            // 0..7 -> d = dblk*8..+8
            const __nv_bfloat16* gh = Vh_ + base + (size_t)(kt * 64 + rv) * DD + dblk * 8;
            const __nv_bfloat16* gl = Vl_ + base + (size_t)(kt * 64 + rv) * DD + dblk * 8;
            uint4 h0 = *(const uint4*)gh;
            uint4 h1 = *(const uint4*)(gh + DD);
            uint4 l0 = *(const uint4*)gl;
            uint4 l1 = *(const uint4*)(gl + DD);
            const uint16_t* h0p = (const uint16_t*)&h0;
            const uint16_t* h1p = (const uint16_t*)&h1;
            const uint16_t* l0p = (const uint16_t*)&l0;
            const uint16_t* l1p = (const uint16_t*)&l1;
            #pragma unroll
            for (int d = 0; d < 8; d++) {
                const uint32_t off = (uint32_t)((dblk * 8 + d) * 144 + rv * 2);
                *(uint32_t*)(sm + (uVh - sb) + off) =
                    (uint32_t)h0p[d] | ((uint32_t)h1p[d] << 16);
                *(uint32_t*)(sm + (uVl - sb) + off) =
                    (uint32_t)l0p[d] | ((uint32_t)l1p[d] << 16);
            }
        }
        CP_WAIT0();
        __syncthreads();

        // ---- scores S = Q @ K^T (split 3-term) ----
        float s[8][4] = {};
        #pragma unroll
        for (int ks = 0; ks < 4; ks++) {
            const int kb = ks * 32;
            uint32_t ah[4], al[4], kh[4][4], kl[4][4];
            {
                const uint32_t off = (uint32_t)((w * 16 + arow) * 144 + kb + acb);
                LDSM_X4(ah[0], ah[1], ah[2], ah[3], uQh + off);
                LDSM_X4(al[0], al[1], al[2], al[3], uQl + off);
            }
            #pragma unroll
            for (int p = 0; p < 4; p++) {
                const uint32_t off = (uint32_t)((p * 16 + brow_q) * 144 + kb + bcb);
                LDSM_X4(kh[p][0], kh[p][1], kh[p][2], kh[p][3], uKh + off);
                LDSM_X4(kl[p][0], kl[p][1], kl[p][2], kl[p][3], uKl + off);
            }
            #pragma unroll
            for (int p = 0; p < 4; p++)
                #pragma unroll
                for (int hh = 0; hh < 2; hh++) {
                    float* d = s[p * 2 + hh];
                    mma16816(d, ah, &kh[p][hh * 2]);
                    mma16816(d, ah, &kl[p][hh * 2]);
                    mma16816(d, al, &kh[p][hh * 2]);
                }
        }

        // ---- scale + causal/pad mask ----
        const int qg0 = qt * 128 + w * 16 + r0;
        #pragma unroll
        for (int nt = 0; nt < 8; nt++) {
            const int cg = kt * 64 + nt * 8 + (lane & 3) * 2;
            #pragma unroll
            for (int j = 0; j < 4; j++) {
                const int row_g = (j >> 1) ? qg0 + 8 : qg0;
                const int col_g = cg + (j & 1);
                s[nt][j] *= scale;
                if (col_g > row_g || pm[j >> 1]) s[nt][j] = NEGV;
            }
        }

        // ---- online softmax ----
        #pragma unroll
        for (int half = 0; half < 2; half++) {
            float tm = -1e30f;
            #pragma unroll
            for (int nt = 0; nt < 8; nt++)
                tm = fmaxf(tm, fmaxf(s[nt][half * 2], s[nt][half * 2 + 1]));
            tm = fmaxf(tm, __shfl_xor_sync(0xffffffffu, tm, 1));
            tm = fmaxf(tm, __shfl_xor_sync(0xffffffffu, tm, 2));
            const float mn = fmaxf(m_r[half], tm);
            const float f = __expf(m_r[half] - mn);
            float ps = 0.f;
            #pragma unroll
            for (int nt = 0; nt < 8; nt++) {
                const float p0 = __expf(s[nt][half * 2]     - mn);
                const float p1 = __expf(s[nt][half * 2 + 1] - mn);
                s[nt][half * 2]     = p0;
                s[nt][half * 2 + 1] = p1;
                ps += p0 + p1;
                acc_o[nt][half * 2]     *= f;
                acc_o[nt][half * 2 + 1] *= f;
            }
            ps += __shfl_xor_sync(0xffffffffu, ps, 1);
            ps += __shfl_xor_sync(0xffffffffu, ps, 2);
            l_r[half] = l_r[half] * f + ps;
            m_r[half] = mn;
        }

        // ---- O += P @ V (P from registers, split 3-term) ----
        #pragma unroll
        for (int ks = 0; ks < 4; ks++) {
            uint32_t ph[4], pl[4];
            const int t0 = 2 * ks, t1 = 2 * ks + 1;
            split2(s[t0][0], s[t0][1], ph[0], pl[0]);
            split2(s[t0][2], s[t0][3], ph[1], pl[1]);
            split2(s[t1][0], s[t1][1], ph[2], pl[2]);
            split2(s[t1][2], s[t1][3], ph[3], pl[3]);

            const int kb = ks * 32;
            uint32_t vh[4][4], vl[4][4];
            #pragma unroll
            for (int p = 0; p < 4; p++) {
                const uint32_t off = (uint32_t)((p * 16 + brow_q) * 144 + kb + bcb);
                LDSM_X4(vh[p][0], vh[p][1], vh[p][2], vh[p][3], uVh + off);
                LDSM_X4(vl[p][0], vl[p][1], vl[p][2], vl[p][3], uVl + off);
            }
            #pragma unroll
            for (int p = 0; p < 4; p++)
                #pragma unroll
                for (int hh = 0; hh < 2; hh++) {
                    float* d = acc_o[p * 2 + hh];
                    mma16816(d, ph, &vh[p][hh * 2]);
                    mma16816(d, ph, &vl[p][hh * 2]);
                    mma16816(d, pl, &vh[p][hh * 2]);
                }
        }
    }

    // ---- normalize + write split ctx ----
    const float inv0 = 1.0f / l_r[0];
    const float inv1 = 1.0f / l_r[1];
    const int row0 = qt * 128 + w * 16 + r0;
    #pragma unroll
    for (int nt = 0; nt < 8; nt++) {
        const int col = h * DK + nt * 8 + (lane & 3) * 2;
        uint32_t hh, ll;
        split2(acc_o[nt][0] * inv0, acc_o[nt][1] * inv0, hh, ll);
        *(uint32_t*)(Ch + ((size_t)b * SS + row0) * DD + col) = hh;
        *(uint32_t*)(Cl + ((size_t)b * SS + row0) * DD + col) = ll;
        split2(acc_o[nt][2] * inv1, acc_o[nt][3] * inv1, hh, ll);
        *(uint32_t*)(Ch + ((size_t)b * SS + row0 + 8) * DD + col) = hh;
        *(uint32_t*)(Cl + ((size_t)b * SS + row0 + 8) * DD + col) = ll;
    }
}

// ---------------------------------------------------------------------------
// out = LayerNorm(X + R) * w + b ; optional split-bf16 copy of out
// ---------------------------------------------------------------------------
template<bool SPLIT>
__global__ void __launch_bounds__(256) add_ln_kernel(
    const float* __restrict__ X, const float* __restrict__ R,
    const float* __restrict__ w, const float* __restrict__ bb,
    float* __restrict__ out,
    __nv_bfloat16* __restrict__ Oh, __nv_bfloat16* __restrict__ Ol)
{
    const int row = blockIdx.x;
    const int tid = threadIdx.x;
    const float4* x4 = (const float4*)(X + (size_t)row * DD);
    const float4* r4 = (const float4*)(R + (size_t)row * DD);
    float4 v = x4[tid];
    const float4 r = r4[tid];
    v.x += r.x; v.y += r.y; v.z += r.z; v.w += r.w;

    float sum = v.x + v.y + v.z + v.w;
    float sq  = v.x*v.x + v.y*v.y + v.z*v.z + v.w*v.w;
    #pragma unroll
    for (int off = 16; off; off >>= 1) {
        sum += __shfl_xor_sync(0xffffffffu, sum, off);
        sq  += __shfl_xor_sync(0xffffffffu, sq, off);
    }
    __shared__ float ssum[8], ssq[8];
    if ((tid & 31) == 0) { ssum[tid >> 5] = sum; ssq[tid >> 5] = sq; }
    __syncthreads();
    float tot = 0.f, totq = 0.f;
    #pragma unroll
    for (int i = 0; i < 8; i++) { tot += ssum[i]; totq += ssq[i]; }
    const float mu   = tot * (1.0f / DD);
    const float var  = totq * (1.0f / DD) - mu * mu;
    const float rstd = rsqrtf(var + 1e-5f);

    const float4 wv = ((const float4*)w)[tid];
    const float4 bv = ((const float4*)bb)[tid];
    float4 ov;
    ov.x = (v.x - mu) * rstd * wv.x + bv.x;
    ov.y = (v.y - mu) * rstd * wv.y + bv.y;
    ov.z = (v.z - mu) * rstd * wv.z + bv.z;
    ov.w = (v.w - mu) * rstd * wv.w + bv.w;
    ((float4*)(out + (size_t)row * DD))[tid] = ov;
    if (SPLIT) {
        uint32_t h0, l0, h1, l1;
        split2(ov.x, ov.y, h0, l0);
        split2(ov.z, ov.w, h1, l1);
        const size_t o = (size_t)row * DD + tid * 4;
        *(uint32_t*)(Oh + o)     = h0;  *(uint32_t*)(Oh + o + 2) = h1;
        *(uint32_t*)(Ol + o)     = l0;  *(uint32_t*)(Ol + o + 2) = l1;
    }
}

// ---------------------------------------------------------------------------
extern "C" void kernel_launch(void* const* d_in, const int* in_sizes, int n_in,
                              void* d_out, int out_size)
{
    int mi = -1;
    for (int i = 0; i < n_in; i++)
        if (in_sizes[i] == BB * SS) { mi = i; break; }

    const float *Q, *K, *V, *Wq, *Wk, *Wv, *Wo, *l1w, *l1b, *l2w, *l2b, *lnw, *lnb;
    const unsigned char* mask;
    if (mi == 3) {
        Q   = (const float*)d_in[0];  K   = (const float*)d_in[1];
        V   = (const float*)d_in[2];  mask = (const unsigned char*)d_in[3];
        Wq  = (const float*)d_in[4];  Wk  = (const float*)d_in[5];
        Wv  = (const float*)d_in[6];  Wo  = (const float*)d_in[7];
        l1w = (const float*)d_in[8];  l1b = (const float*)d_in[9];
        l2w = (const float*)d_in[10]; l2b = (const float*)d_in[11];
        lnw = (const float*)d_in[12]; lnb = (const float*)d_in[13];
    } else {
        Q   = (const float*)d_in[0];  K   = (const float*)d_in[1];
        V   = (const float*)d_in[2];
        Wq  = (const float*)d_in[3];  Wk  = (const float*)d_in[4];
        Wv  = (const float*)d_in[5];  Wo  = (const float*)d_in[6];
        l1w = (const float*)d_in[7];  l1b = (const float*)d_in[8];
        l2w = (const float*)d_in[9];  l2b = (const float*)d_in[10];
        lnw = (const float*)d_in[11]; lnb = (const float*)d_in[12];
        mask = (const unsigned char*)d_in[13];
    }

    float *gA, *gB, *gC;
    __nv_bfloat16 *bf, *wsp;
    cudaGetSymbolAddress((void**)&gA, g_A);
    cudaGetSymbolAddress((void**)&gB, g_B);
    cudaGetSymbolAddress((void**)&gC, g_C);
    cudaGetSymbolAddress((void**)&bf, g_bf);
    cudaGetSymbolAddress((void**)&wsp, g_w);

    const size_t PSZ = (size_t)MTOK * DD;
    auto P = [&](int i, int half) { return bf + ((size_t)(i * 2 + half)) * PSZ; };
    const size_t WSZ = (size_t)DD * DD;
    auto W = [&](int i, int half) { return wsp + ((size_t)(i * 2 + half)) * WSZ; };

    cudaFuncSetAttribute(mma_gemm<false, false, false, true>,
                         cudaFuncAttributeMaxDynamicSharedMemorySize, GEMM_SMEM);
    cudaFuncSetAttribute(mma_gemm<false, false, true, false>,
                         cudaFuncAttributeMaxDynamicSharedMemorySize, GEMM_SMEM);
    cudaFuncSetAttribute(mma_gemm<true, true, false, true>,
                         cudaFuncAttributeMaxDynamicSharedMemorySize, GEMM_SMEM);
    cudaFuncSetAttribute(mma_gemm<true, false, true, false>,
                         cudaFuncAttributeMaxDynamicSharedMemorySize, GEMM_SMEM);
    cudaFuncSetAttribute(attn_mma_kernel,
                         cudaFuncAttributeMaxDynamicSharedMemorySize, ATT_SMEM);

    // --- converts ---
    const dim3 wtGrid(DD / 32, DD / 32);
    conv_w_t<<<wtGrid, dim3(32, 8)>>>(Wq, W(0,0), W(0,1));
    conv_w_t<<<wtGrid, dim3(32, 8)>>>(Wk, W(1,0), W(1,1));
    conv_w_t<<<wtGrid, dim3(32, 8)>>>(Wv, W(2,0), W(2,1));
    conv_w_t<<<wtGrid, dim3(32, 8)>>>(Wo, W(3,0), W(3,1));
    conv_a<<<(int)(WSZ / 1024), 256>>>(l1w, W(4,0), W(4,1));   // already [N,K]
    conv_a<<<(int)(WSZ / 1024), 256>>>(l2w, W(5,0), W(5,1));
    conv_a<<<(int)(PSZ / 1024), 256>>>(Q, P(0,0), P(0,1));
    conv_a<<<(int)(PSZ / 1024), 256>>>(K, P(1,0), P(1,1));
    conv_a<<<(int)(PSZ / 1024), 256>>>(V, P(2,0), P(2,1));

    const dim3 gGrid(DD / 128, MTOK / 128);   // (8, 128)

    // --- QKV projections -> split outputs ---
    mma_gemm<false, false, false, true><<<gGrid, 256, GEMM_SMEM>>>(
        P(0,0), P(0,1), W(0,0), W(0,1), nullptr, nullptr, P(3,0), P(3,1));   // Qp
    mma_gemm<false, false, false, true><<<gGrid, 256, GEMM_SMEM>>>(
        P(1,0), P(1,1), W(1,0), W(1,1), nullptr, nullptr, P(0,0), P(0,1));   // Kp
    mma_gemm<false, false, false, true><<<gGrid, 256, GEMM_SMEM>>>(
        P(2,0), P(2,1), W(2,0), W(2,1), nullptr, nullptr, P(1,0), P(1,1));   // Vp

    // --- attention -> split ctx ---
    attn_mma_kernel<<<dim3(SS / 128, BB * HH), 256, ATT_SMEM>>>(
        P(3,0), P(3,1), P(0,0), P(0,1), P(1,0), P(1,1), mask, P(2,0), P(2,1));

    // --- output projection -> fp32 ---
    mma_gemm<false, false, true, false><<<gGrid, 256, GEMM_SMEM>>>(
        P(2,0), P(2,1), W(3,0), W(3,1), nullptr, gA, nullptr, nullptr);

    // --- X = LN(V_att + Q): fp32 + splits ---
    add_ln_kernel<true><<<MTOK, 256>>>(gA, Q, lnw, lnb, gB, P(3,0), P(3,1));

    // --- FFN ---
    mma_gemm<true, true, false, true><<<gGrid, 256, GEMM_SMEM>>>(
        P(3,0), P(3,1), W(4,0), W(4,1), l1b, nullptr, P(0,0), P(0,1));
    mma_gemm<true, false, true, false><<<gGrid, 256, GEMM_SMEM>>>(
        P(0,0), P(0,1), W(5,0), W(5,1), l2b, gC, nullptr, nullptr);

    // --- out = LN(ffn + X) ---
    add_ln_kernel<false><<<MTOK, 256>>>(gC, gB, lnw, lnb, (float*)d_out, nullptr, nullptr);
}

// round 9
// speedup vs baseline: 2.5642x; 1.0503x over previous
#include <cuda_runtime.h>
#include <cuda_bf16.h>
#include <stdint.h>

// Problem constants
#define BB 16
#define SS 1024
#define DD 1024
#define HH 16
#define DK 64
#define MTOK (BB*SS)          // 16384 token rows

// Scratch buffers (device globals — no allocation allowed)
__device__ float g_A[(size_t)MTOK * DD];
__device__ float g_B[(size_t)MTOK * DD];
__device__ float g_C[(size_t)MTOK * DD];
// 4 pairs of split-bf16 activation buffers (hi/lo), each MTOK*DD
__device__ __nv_bfloat16 g_bf[(size_t)4 * 2 * MTOK * DD];
// 6 weight pairs (hi/lo), each DD*DD, all stored [N,K]
__device__ __nv_bfloat16 g_w[(size_t)6 * 2 * DD * DD];

// ===========================================================================
// Helpers
// ===========================================================================
__device__ __forceinline__ uint32_t smem_u32(const void* p) {
    uint32_t a;
    asm("{ .reg .u64 t; cvta.to.shared.u64 t, %1; cvt.u32.u64 %0, t; }" : "=r"(a) : "l"(p));
    return a;
}

#define LDSM_X4(R0, R1, R2, R3, addr)                                          \
    asm volatile("ldmatrix.sync.aligned.m8n8.x4.shared.b16 {%0,%1,%2,%3}, [%4];" \
        : "=r"(R0), "=r"(R1), "=r"(R2), "=r"(R3) : "r"(addr))

__device__ __forceinline__ void mma16816(float* d, const uint32_t* a, const uint32_t* b) {
    asm volatile(
        "mma.sync.aligned.m16n8k16.row.col.f32.bf16.bf16.f32 "
        "{%0,%1,%2,%3}, {%4,%5,%6,%7}, {%8,%9}, {%0,%1,%2,%3};"
        : "+f"(d[0]), "+f"(d[1]), "+f"(d[2]), "+f"(d[3])
        : "r"(a[0]), "r"(a[1]), "r"(a[2]), "r"(a[3]), "r"(b[0]), "r"(b[1]));
}

__device__ __forceinline__ void split2(float a, float b, uint32_t& hi, uint32_t& lo) {
    __nv_bfloat16 ah = __float2bfloat16_rn(a);
    __nv_bfloat16 bh = __float2bfloat16_rn(b);
    __nv_bfloat16 al = __float2bfloat16_rn(a - __bfloat162float(ah));
    __nv_bfloat16 bl = __float2bfloat16_rn(b - __bfloat162float(bh));
    hi = (uint32_t)__bfloat16_as_ushort(ah) | ((uint32_t)__bfloat16_as_ushort(bh) << 16);
    lo = (uint32_t)__bfloat16_as_ushort(al) | ((uint32_t)__bfloat16_as_ushort(bl) << 16);
}

#define CP16(sm, gm) asm volatile("cp.async.cg.shared.global [%0], [%1], 16;" :: "r"(sm), "l"(gm))
#define CP_COMMIT()  asm volatile("cp.async.commit_group;")
#define CP_WAIT0()   asm volatile("cp.async.wait_group 0;" ::: "memory")
#define CP_WAIT2()   asm volatile("cp.async.wait_group 2;" ::: "memory")

// ===========================================================================
// Convert kernels (one-time per launch)
// ===========================================================================
__global__ void conv_a(const float* __restrict__ X,
                       __nv_bfloat16* __restrict__ Xh, __nv_bfloat16* __restrict__ Xl)
{
    const size_t i = ((size_t)blockIdx.x * 256 + threadIdx.x) * 4;
    const float4 v = *(const float4*)(X + i);
    uint32_t h0, l0, h1, l1;
    split2(v.x, v.y, h0, l0);
    split2(v.z, v.w, h1, l1);
    *(uint32_t*)(Xh + i)     = h0;  *(uint32_t*)(Xh + i + 2) = h1;
    *(uint32_t*)(Xl + i)     = l0;  *(uint32_t*)(Xl + i + 2) = l1;
}

// W [K,N] fp32 -> Wh/Wl [N,K] bf16 (transpose via smem)
__global__ void conv_w_t(const float* __restrict__ W,
                         __nv_bfloat16* __restrict__ Wh, __nv_bfloat16* __restrict__ Wl)
{
    __shared__ float t[32][33];
    const int n0 = blockIdx.x * 32;
    const int k0 = blockIdx.y * 32;
    const int tx = threadIdx.x, ty = threadIdx.y;
    #pragma unroll
    for (int j = ty; j < 32; j += 8)
        t[j][tx] = W[(size_t)(k0 + j) * DD + n0 + tx];
    __syncthreads();
    const int k = k0 + tx;
    #pragma unroll
    for (int j = ty; j < 32; j += 8) {
        const float v = t[tx][j];
        const __nv_bfloat16 hi = __float2bfloat16_rn(v);
        const __nv_bfloat16 lo = __float2bfloat16_rn(v - __bfloat162float(hi));
        Wh[(size_t)(n0 + j) * DD + k] = hi;
        Wl[(size_t)(n0 + j) * DD + k] = lo;
    }
}

// ===========================================================================
// Split-bf16 mma.sync GEMM: C = A[M,K] @ B^T, pre-split operands.
// CTA 128x128, BK=32, 4-stage cp.async pipeline.
// ===========================================================================
#define RSTRIDE 80
#define T_BYTES (128 * RSTRIDE)
#define STG_BYTES (4 * T_BYTES)            // 40960
#define GSTAGES 4
#define GEMM_SMEM (GSTAGES * STG_BYTES)    // 163840
#define NCHUNK (DD / 32)

template<bool BIAS, bool RELU, bool OUTF32, bool OUTSPLIT>
__global__ void __launch_bounds__(256, 1) mma_gemm(
    const __nv_bfloat16* __restrict__ Ah, const __nv_bfloat16* __restrict__ Al,
    const __nv_bfloat16* __restrict__ Bh, const __nv_bfloat16* __restrict__ Bl,
    const float* __restrict__ bias,
    float* __restrict__ Cf,
    __nv_bfloat16* __restrict__ Ch, __nv_bfloat16* __restrict__ Cl)
{
    extern __shared__ char smem[];
    const uint32_t sbase = smem_u32(smem);
    const int tid  = threadIdx.x;
    const int lane = tid & 31;
    const int wid  = tid >> 5;
    const int wm   = wid & 3;
    const int wn   = wid >> 2;
    const int n0   = blockIdx.x * 128;
    const int m0   = blockIdx.y * 128;

    float acc[2][8][4] = {};

    auto issue = [&](int c, int s) {
        const int k0 = c * 32;
        const uint32_t st = sbase + s * STG_BYTES;
        #pragma unroll
        for (int i = 0; i < 8; i++) {
            const int id   = tid + 256 * i;
            const int tile = id >> 9;                  // 0:Ah 1:Al 2:Bh 3:Bl
            const int r    = (id >> 2) & 127;
            const int seg  = id & 3;
            const __nv_bfloat16* g =
                (tile == 0 ? Ah : tile == 1 ? Al : tile == 2 ? Bh : Bl)
                + (size_t)((tile < 2 ? m0 : n0) + r) * DD + k0 + seg * 8;
            CP16(st + tile * T_BYTES + r * RSTRIDE + seg * 16, g);
        }
    };

    auto compute = [&](uint32_t stg) {
        const uint32_t sAh = stg;
        const uint32_t sAl = stg + T_BYTES;
        const uint32_t sBh = stg + 2 * T_BYTES;
        const uint32_t sBl = stg + 3 * T_BYTES;
        #pragma unroll
        for (int ks = 0; ks < 2; ks++) {
            const int kb = ks * 16 * 2;
            uint32_t ah[2][4], al[2][4], bh[4][4], bl[4][4];
            const int arow = (lane & 15);
            const int acb  = kb + ((lane >> 4) * 8) * 2;
            #pragma unroll
            for (int mt = 0; mt < 2; mt++) {
                const uint32_t off = (uint32_t)((wm * 32 + mt * 16 + arow) * RSTRIDE + acb);
                LDSM_X4(ah[mt][0], ah[mt][1], ah[mt][2], ah[mt][3], sAh + off);
                LDSM_X4(al[mt][0], al[mt][1], al[mt][2], al[mt][3], sAl + off);
            }
            const int q  = lane >> 3;
            const int lr = lane & 7;
            const int brow_q = ((q & 2) ? 8 : 0) + lr;
            const int bcb    = kb + ((q & 1) * 8) * 2;
            #pragma unroll
            for (int p = 0; p < 4; p++) {
                const uint32_t off = (uint32_t)((wn * 64 + p * 16 + brow_q) * RSTRIDE + bcb);
                LDSM_X4(bh[p][0], bh[p][1], bh[p][2], bh[p][3], sBh + off);
                LDSM_X4(bl[p][0], bl[p][1], bl[p][2], bl[p][3], sBl + off);
            }
            #pragma unroll
            for (int mt = 0; mt < 2; mt++)
                #pragma unroll
                for (int p = 0; p < 4; p++)
                    #pragma unroll
                    for (int h = 0; h < 2; h++) {
                        float* d = acc[mt][p * 2 + h];
                        mma16816(d, ah[mt], &bh[p][h * 2]);
                        mma16816(d, ah[mt], &bl[p][h * 2]);
                        mma16816(d, al[mt], &bh[p][h * 2]);
                    }
        }
    };

    // 4-stage pipeline: 3 chunks in flight
    issue(0, 0); CP_COMMIT();
    issue(1, 1); CP_COMMIT();
    issue(2, 2); CP_COMMIT();
    for (int c = 0; c < NCHUNK; c++) {
        CP_WAIT2();            // groups <= c+2 outstanding -> chunk c arrived
        __syncthreads();
        if (c + 3 < NCHUNK) issue(c + 3, (c + 3) & 3);
        CP_COMMIT();           // empty commit keeps group accounting exact
        compute(sbase + (c & 3) * STG_BYTES);
    }

    // Epilogue
    #pragma unroll
    for (int mt = 0; mt < 2; mt++) {
        const int row = m0 + wm * 32 + mt * 16 + (lane >> 2);
        #pragma unroll
        for (int nt = 0; nt < 8; nt++) {
            const int col = n0 + wn * 64 + nt * 8 + (lane & 3) * 2;
            float b0 = 0.f, b1 = 0.f;
            if (BIAS) { b0 = __ldg(bias + col); b1 = __ldg(bias + col + 1); }
            float2 v01, v23;
            v01.x = acc[mt][nt][0] + b0;  v01.y = acc[mt][nt][1] + b1;
            v23.x = acc[mt][nt][2] + b0;  v23.y = acc[mt][nt][3] + b1;
            if (RELU) {
                v01.x = fmaxf(v01.x, 0.f); v01.y = fmaxf(v01.y, 0.f);
                v23.x = fmaxf(v23.x, 0.f); v23.y = fmaxf(v23.y, 0.f);
            }
            if (OUTF32) {
                *(float2*)(Cf + (size_t)row * DD + col)       = v01;
                *(float2*)(Cf + (size_t)(row + 8) * DD + col) = v23;
            }
            if (OUTSPLIT) {
                uint32_t h, l;
                split2(v01.x, v01.y, h, l);
                *(uint32_t*)(Ch + (size_t)row * DD + col) = h;
                *(uint32_t*)(Cl + (size_t)row * DD + col) = l;
                split2(v23.x, v23.y, h, l);
                *(uint32_t*)(Ch + (size_t)(row + 8) * DD + col) = h;
                *(uint32_t*)(Cl + (size_t)(row + 8) * DD + col) = l;
            }
        }
    }
}

// ===========================================================================
// Tensor-core flash attention, pre-split bf16 inputs, double-buffered K/V.
// CTA = (qt of 128 rows, b*h), 256 threads / 8 warps; k-tile 64, DK=64.
// ===========================================================================
#define AST 72
#define QTILE_B (128 * AST * 2)            // 18432
#define KTILE_B (64 * AST * 2)             // 9216
#define KVSTG (4 * KTILE_B)                // Kh Kl Vh Vl per stage: 36864
#define ATT_SMEM (2 * QTILE_B + 2 * KVSTG) // 110592

__global__ void __launch_bounds__(256) attn_mma_kernel(
    const __nv_bfloat16* __restrict__ Qh_, const __nv_bfloat16* __restrict__ Ql_,
    const __nv_bfloat16* __restrict__ Kh_, const __nv_bfloat16* __restrict__ Kl_,
    const __nv_bfloat16* __restrict__ Vh_, const __nv_bfloat16* __restrict__ Vl_,
    const unsigned char* __restrict__ mask,
    __nv_bfloat16* __restrict__ Ch, __nv_bfloat16* __restrict__ Cl)
{
    extern __shared__ char sm[];
    const uint32_t sb = smem_u32(sm);
    const int tid  = threadIdx.x;
    const int lane = tid & 31;
    const int w    = tid >> 5;
    const int qt   = blockIdx.x;           // 0..7
    const int bh   = blockIdx.y;
    const int b    = bh >> 4;
    const int h    = bh & 15;

    const uint32_t uQh = sb;
    const uint32_t uQl = sb + QTILE_B;
    const uint32_t kvBase = sb + 2 * QTILE_B;

    const size_t base = (size_t)b * SS * DD + (size_t)h * DK;

    // ---- Q tile cp.async ----
    #pragma unroll
    for (int i = 0; i < 8; i++) {
        const int id   = tid + 256 * i;
        const int tile = id >> 10;
        const int r    = (id >> 3) & 127;
        const int seg  = id & 7;
        const __nv_bfloat16* g = (tile ? Ql_ : Qh_)
            + base + (size_t)(qt * 128 + r) * DD + seg * 8;
        CP16(sb + tile * QTILE_B + r * 144 + seg * 16, g);
    }
    CP_COMMIT();

    auto issueK = [&](int kt, int s) {
        const uint32_t st = kvBase + s * KVSTG;
        #pragma unroll
        for (int i = 0; i < 4; i++) {
            const int id   = tid + 256 * i;
            const int tile = id >> 9;          // 0 hi, 1 lo
            const int r    = (id >> 3) & 63;
            const int seg  = id & 7;
            const __nv_bfloat16* g = (tile ? Kl_ : Kh_)
                + base + (size_t)(kt * 64 + r) * DD + seg * 8;
            CP16(st + tile * KTILE_B + r * 144 + seg * 16, g);
        }
    };

    const int rv   = (lane) * 2;   // within-warp seq pair base handled below
    const int vrow = (tid & 31) * 2;
    const int dblk = tid >> 5;
    (void)rv;
    uint4 vh0, vh1, vl0, vl1;
    auto ldgV = [&](int kt) {
        const __nv_bfloat16* gh = Vh_ + base + (size_t)(kt * 64 + vrow) * DD + dblk * 8;
        const __nv_bfloat16* gl = Vl_ + base + (size_t)(kt * 64 + vrow) * DD + dblk * 8;
        vh0 = *(const uint4*)gh;  vh1 = *(const uint4*)(gh + DD);
        vl0 = *(const uint4*)gl;  vl1 = *(const uint4*)(gl + DD);
    };
    auto stsV = [&](int s) {
        const uint32_t st = kvBase + s * KVSTG;
        const uint16_t* h0p = (const uint16_t*)&vh0;
        const uint16_t* h1p = (const uint16_t*)&vh1;
        const uint16_t* l0p = (const uint16_t*)&vl0;
        const uint16_t* l1p = (const uint16_t*)&vl1;
        #pragma unroll
        for (int d = 0; d < 8; d++) {
            const uint32_t off = (uint32_t)((dblk * 8 + d) * 144 + vrow * 2);
            *(uint32_t*)(sm + (st - sb) + 2 * KTILE_B + off) =
                (uint32_t)h0p[d] | ((uint32_t)h1p[d] << 16);
            *(uint32_t*)(sm + (st - sb) + 3 * KTILE_B + off) =
                (uint32_t)l0p[d] | ((uint32_t)l1p[d] << 16);
        }
    };

    const int r0 = lane >> 2;
    unsigned char pm[2];
    pm[0] = mask[(size_t)b * SS + qt * 128 + w * 16 + r0];
    pm[1] = mask[(size_t)b * SS + qt * 128 + w * 16 + r0 + 8];

    float m_r[2] = {-1e30f, -1e30f};
    float l_r[2] = {0.f, 0.f};
    float acc_o[8][4] = {};

    const float NEGV  = -4294967295.0f;
    const float scale = 1.0f / 8.000001f;

    const int arow   = lane & 15;
    const int acb    = ((lane >> 4) * 8) * 2;
    const int qq     = lane >> 3;
    const int lr     = lane & 7;
    const int brow_q = ((qq & 2) ? 8 : 0) + lr;
    const int bcb    = ((qq & 1) * 8) * 2;

    // ---- prologue: K(0) + V(0) ----
    issueK(0, 0); CP_COMMIT();
    ldgV(0);
    CP_WAIT0();
    __syncthreads();       // Q, K0 visible
    stsV(0);
    __syncthreads();       // V0 visible

    const int kmax = 2 * qt + 1;
    for (int kt = 0; kt <= kmax; kt++) {
        const int s = kt & 1;
        const uint32_t st = kvBase + s * KVSTG;
        const uint32_t uKh = st;
        const uint32_t uKl = st + KTILE_B;
        const uint32_t uVh = st + 2 * KTILE_B;
        const uint32_t uVl = st + 3 * KTILE_B;

        // prefetch next K/V overlapped with this iteration's compute
        if (kt < kmax) {
            issueK(kt + 1, s ^ 1); CP_COMMIT();
            ldgV(kt + 1);
        }

        // ---- scores S = Q @ K^T ----
        float sc[8][4] = {};
        #pragma unroll
        for (int ks = 0; ks < 4; ks++) {
            const int kb = ks * 32;
            uint32_t ah[4], al[4], kh[4][4], kl[4][4];
            {
                const uint32_t off = (uint32_t)((w * 16 + arow) * 144 + kb + acb);
                LDSM_X4(ah[0], ah[1], ah[2], ah[3], uQh + off);
                LDSM_X4(al[0], al[1], al[2], al[3], uQl + off);
            }
            #pragma unroll
            for (int p = 0; p < 4; p++) {
                const uint32_t off = (uint32_t)((p * 16 + brow_q) * 144 + kb + bcb);
                LDSM_X4(kh[p][0], kh[p][1], kh[p][2], kh[p][3], uKh + off);
                LDSM_X4(kl[p][0], kl[p][1], kl[p][2], kl[p][3], uKl + off);
            }
            #pragma unroll
            for (int p = 0; p < 4; p++)
                #pragma unroll
                for (int hh = 0; hh < 2; hh++) {
                    float* d = sc[p * 2 + hh];
                    mma16816(d, ah, &kh[p][hh * 2]);
                    mma16816(d, ah, &kl[p][hh * 2]);
                    mma16816(d, al, &kh[p][hh * 2]);
                }
        }

        // ---- scale + causal/pad mask ----
        const int qg0 = qt * 128 + w * 16 + r0;
        #pragma unroll
        for (int nt = 0; nt < 8; nt++) {
            const int cg = kt * 64 + nt * 8 + (lane & 3) * 2;
            #pragma unroll
            for (int j = 0; j < 4; j++) {
                const int row_g = (j >> 1) ? qg0 + 8 : qg0;
                const int col_g = cg + (j & 1);
                sc[nt][j] *= scale;
                if (col_g > row_g || pm[j >> 1]) sc[nt][j] = NEGV;
            }
        }

        // ---- online softmax ----
        #pragma unroll
        for (int half = 0; half < 2; half++) {
            float tm = -1e30f;
            #pragma unroll
            for (int nt = 0; nt < 8; nt++)
                tm = fmaxf(tm, fmaxf(sc[nt][half * 2], sc[nt][half * 2 + 1]));
            tm = fmaxf(tm, __shfl_xor_sync(0xffffffffu, tm, 1));
            tm = fmaxf(tm, __shfl_xor_sync(0xffffffffu, tm, 2));
            const float mn = fmaxf(m_r[half], tm);
            const float f = __expf(m_r[half] - mn);
            float ps = 0.f;
            #pragma unroll
            for (int nt = 0; nt < 8; nt++) {
                const float p0 = __expf(sc[nt][half * 2]     - mn);
                const float p1 = __expf(sc[nt][half * 2 + 1] - mn);
                sc[nt][half * 2]     = p0;
                sc[nt][half * 2 + 1] = p1;
                ps += p0 + p1;
                acc_o[nt][half * 2]     *= f;
                acc_o[nt][half * 2 + 1] *= f;
            }
            ps += __shfl_xor_sync(0xffffffffu, ps, 1);
            ps += __shfl_xor_sync(0xffffffffu, ps, 2);
            l_r[half] = l_r[half] * f + ps;
            m_r[half] = mn;
        }

        // store next V into the spare stage (no barrier needed: disjoint buffers)
        if (kt < kmax) stsV(s ^ 1);

        // ---- O += P @ V ----
        #pragma unroll
        for (int ks = 0; ks < 4; ks++) {
            uint32_t ph[4], pl[4];
            const int t0 = 2 * ks, t1 = 2 * ks + 1;
            split2(sc[t0][0], sc[t0][1], ph[0], pl[0]);
            split2(sc[t0][2], sc[t0][3], ph[1], pl[1]);
            split2(sc[t1][0], sc[t1][1], ph[2], pl[2]);
            split2(sc[t1][2], sc[t1][3], ph[3], pl[3]);

            const int kb = ks * 32;
            uint32_t vh[4][4], vl[4][4];
            #pragma unroll
            for (int p = 0; p < 4; p++) {
                const uint32_t off = (uint32_t)((p * 16 + brow_q) * 144 + kb + bcb);
                LDSM_X4(vh[p][0], vh[p][1], vh[p][2], vh[p][3], uVh + off);
                LDSM_X4(vl[p][0], vl[p][1], vl[p][2], vl[p][3], uVl + off);
            }
            #pragma unroll
            for (int p = 0; p < 4; p++)
                #pragma unroll
                for (int hh = 0; hh < 2; hh++) {
                    float* d = acc_o[p * 2 + hh];
                    mma16816(d, ph, &vh[p][hh * 2]);
                    mma16816(d, ph, &vl[p][hh * 2]);
                    mma16816(d, pl, &vh[p][hh * 2]);
                }
        }

        if (kt < kmax) {
            CP_WAIT0();        // K(kt+1) arrived (overlapped with compute above)
            __syncthreads();   // K + V stores visible; all warps done with stage s
        }
    }

    // ---- normalize + write split ctx ----
    const float inv0 = 1.0f / l_r[0];
    const float inv1 = 1.0f / l_r[1];
    const int row0 = qt * 128 + w * 16 + r0;
    #pragma unroll
    for (int nt = 0; nt < 8; nt++) {
        const int col = h * DK + nt * 8 + (lane & 3) * 2;
        uint32_t hh, ll;
        split2(acc_o[nt][0] * inv0, acc_o[nt][1] * inv0, hh, ll);
        *(uint32_t*)(Ch + ((size_t)b * SS + row0) * DD + col) = hh;
        *(uint32_t*)(Cl + ((size_t)b * SS + row0) * DD + col) = ll;
        split2(acc_o[nt][2] * inv1, acc_o[nt][3] * inv1, hh, ll);
        *(uint32_t*)(Ch + ((size_t)b * SS + row0 + 8) * DD + col) = hh;
        *(uint32_t*)(Cl + ((size_t)b * SS + row0 + 8) * DD + col) = ll;
    }
}

// ---------------------------------------------------------------------------
// out = LayerNorm(X + R) * w + b ; optional split-bf16 copy of out
// ---------------------------------------------------------------------------
template<bool SPLIT>
__global__ void __launch_bounds__(256) add_ln_kernel(
    const float* __restrict__ X, const float* __restrict__ R,
    const float* __restrict__ w, const float* __restrict__ bb,
    float* __restrict__ out,
    __nv_bfloat16* __restrict__ Oh, __nv_bfloat16* __restrict__ Ol)
{
    const int row = blockIdx.x;
    const int tid = threadIdx.x;
    const float4* x4 = (const float4*)(X + (size_t)row * DD);
    const float4* r4 = (const float4*)(R + (size_t)row * DD);
    float4 v = x4[tid];
    const float4 r = r4[tid];
    v.x += r.x; v.y += r.y; v.z += r.z; v.w += r.w;

    float sum = v.x + v.y + v.z + v.w;
    float sq  = v.x*v.x + v.y*v.y + v.z*v.z + v.w*v.w;
    #pragma unroll
    for (int off = 16; off; off >>= 1) {
        sum += __shfl_xor_sync(0xffffffffu, sum, off);
        sq  += __shfl_xor_sync(0xffffffffu, sq, off);
    }
    __shared__ float ssum[8], ssq[8];
    if ((tid & 31) == 0) { ssum[tid >> 5] = sum; ssq[tid >> 5] = sq; }
    __syncthreads();
    float tot = 0.f, totq = 0.f;
    #pragma unroll
    for (int i = 0; i < 8; i++) { tot += ssum[i]; totq += ssq[i]; }
    const float mu   = tot * (1.0f / DD);
    const float var  = totq * (1.0f / DD) - mu * mu;
    const float rstd = rsqrtf(var + 1e-5f);

    const float4 wv = ((const float4*)w)[tid];
    const float4 bv = ((const float4*)bb)[tid];
    float4 ov;
    ov.x = (v.x - mu) * rstd * wv.x + bv.x;
    ov.y = (v.y - mu) * rstd * wv.y + bv.y;
    ov.z = (v.z - mu) * rstd * wv.z + bv.z;
    ov.w = (v.w - mu) * rstd * wv.w + bv.w;
    ((float4*)(out + (size_t)row * DD))[tid] = ov;
    if (SPLIT) {
        uint32_t h0, l0, h1, l1;
        split2(ov.x, ov.y, h0, l0);
        split2(ov.z, ov.w, h1, l1);
        const size_t o = (size_t)row * DD + tid * 4;
        *(uint32_t*)(Oh + o)     = h0;  *(uint32_t*)(Oh + o + 2) = h1;
        *(uint32_t*)(Ol + o)     = l0;  *(uint32_t*)(Ol + o + 2) = l1;
    }
}

// ---------------------------------------------------------------------------
extern "C" void kernel_launch(void* const* d_in, const int* in_sizes, int n_in,
                              void* d_out, int out_size)
{
    int mi = -1;
    for (int i = 0; i < n_in; i++)
        if (in_sizes[i] == BB * SS) { mi = i; break; }

    const float *Q, *K, *V, *Wq, *Wk, *Wv, *Wo, *l1w, *l1b, *l2w, *l2b, *lnw, *lnb;
    const unsigned char* mask;
    if (mi == 3) {
        Q   = (const float*)d_in[0];  K   = (const float*)d_in[1];
        V   = (const float*)d_in[2];  mask = (const unsigned char*)d_in[3];
        Wq  = (const float*)d_in[4];  Wk  = (const float*)d_in[5];
        Wv  = (const float*)d_in[6];  Wo  = (const float*)d_in[7];
        l1w = (const float*)d_in[8];  l1b = (const float*)d_in[9];
        l2w = (const float*)d_in[10]; l2b = (const float*)d_in[11];
        lnw = (const float*)d_in[12]; lnb = (const float*)d_in[13];
    } else {
        Q   = (const float*)d_in[0];  K   = (const float*)d_in[1];
        V   = (const float*)d_in[2];
        Wq  = (const float*)d_in[3];  Wk  = (const float*)d_in[4];
        Wv  = (const float*)d_in[5];  Wo  = (const float*)d_in[6];
        l1w = (const float*)d_in[7];  l1b = (const float*)d_in[8];
        l2w = (const float*)d_in[9];  l2b = (const float*)d_in[10];
        lnw = (const float*)d_in[11]; lnb = (const float*)d_in[12];
        mask = (const unsigned char*)d_in[13];
    }

    float *gA, *gB, *gC;
    __nv_bfloat16 *bf, *wsp;
    cudaGetSymbolAddress((void**)&gA, g_A);
    cudaGetSymbolAddress((void**)&gB, g_B);
    cudaGetSymbolAddress((void**)&gC, g_C);
    cudaGetSymbolAddress((void**)&bf, g_bf);
    cudaGetSymbolAddress((void**)&wsp, g_w);

    const size_t PSZ = (size_t)MTOK * DD;
    auto P = [&](int i, int half) { return bf + ((size_t)(i * 2 + half)) * PSZ; };
    const size_t WSZ = (size_t)DD * DD;
    auto W = [&](int i, int half) { return wsp + ((size_t)(i * 2 + half)) * WSZ; };

    cudaFuncSetAttribute(mma_gemm<false, false, false, true>,
                         cudaFuncAttributeMaxDynamicSharedMemorySize, GEMM_SMEM);
    cudaFuncSetAttribute(mma_gemm<false, false, true, false>,
                         cudaFuncAttributeMaxDynamicSharedMemorySize, GEMM_SMEM);
    cudaFuncSetAttribute(mma_gemm<true, true, false, true>,
                         cudaFuncAttributeMaxDynamicSharedMemorySize, GEMM_SMEM);
    cudaFuncSetAttribute(mma_gemm<true, false, true, false>,
                         cudaFuncAttributeMaxDynamicSharedMemorySize, GEMM_SMEM);
    cudaFuncSetAttribute(attn_mma_kernel,
                         cudaFuncAttributeMaxDynamicSharedMemorySize, ATT_SMEM);

    // --- converts ---
    const dim3 wtGrid(DD / 32, DD / 32);
    conv_w_t<<<wtGrid, dim3(32, 8)>>>(Wq, W(0,0), W(0,1));
    conv_w_t<<<wtGrid, dim3(32, 8)>>>(Wk, W(1,0), W(1,1));
    conv_w_t<<<wtGrid, dim3(32, 8)>>>(Wv, W(2,0), W(2,1));
    conv_w_t<<<wtGrid, dim3(32, 8)>>>(Wo, W(3,0), W(3,1));
    conv_a<<<(int)(WSZ / 1024), 256>>>(l1w, W(4,0), W(4,1));
    conv_a<<<(int)(WSZ / 1024), 256>>>(l2w, W(5,0), W(5,1));
    conv_a<<<(int)(PSZ / 1024), 256>>>(Q, P(0,0), P(0,1));
    conv_a<<<(int)(PSZ / 1024), 256>>>(K, P(1,0), P(1,1));
    conv_a<<<(int)(PSZ / 1024), 256>>>(V, P(2,0), P(2,1));

    const dim3 gGrid(DD / 128, MTOK / 128);   // (8, 128)

    // --- QKV projections -> split outputs ---
    mma_gemm<false, false, false, true><<<gGrid, 256, GEMM_SMEM>>>(
        P(0,0), P(0,1), W(0,0), W(0,1), nullptr, nullptr, P(3,0), P(3,1));   // Qp
    mma_gemm<false, false, false, true><<<gGrid, 256, GEMM_SMEM>>>(
        P(1,0), P(1,1), W(1,0), W(1,1), nullptr, nullptr, P(0,0), P(0,1));   // Kp
    mma_gemm<false, false, false, true><<<gGrid, 256, GEMM_SMEM>>>(
        P(2,0), P(2,1), W(2,0), W(2,1), nullptr, nullptr, P(1,0), P(1,1));   // Vp

    // --- attention -> split ctx ---
    attn_mma_kernel<<<dim3(SS / 128, BB * HH), 256, ATT_SMEM>>>(
        P(3,0), P(3,1), P(0,0), P(0,1), P(1,0), P(1,1), mask, P(2,0), P(2,1));

    // --- output projection -> fp32 ---
    mma_gemm<false, false, true, false><<<gGrid, 256, GEMM_SMEM>>>(
        P(2,0), P(2,1), W(3,0), W(3,1), nullptr, gA, nullptr, nullptr);

    // --- X = LN(V_att + Q): fp32 + splits ---
    add_ln_kernel<true><<<MTOK, 256>>>(gA, Q, lnw, lnb, gB, P(3,0), P(3,1));

    // --- FFN ---
    mma_gemm<true, true, false, true><<<gGrid, 256, GEMM_SMEM>>>(
        P(3,0), P(3,1), W(4,0), W(4,1), l1b, nullptr, P(0,0), P(0,1));
    mma_gemm<true, false, true, false><<<gGrid, 256, GEMM_SMEM>>>(
        P(0,0), P(0,1), W(5,0), W(5,1), l2b, gC, nullptr, nullptr);

    // --- out = LN(ffn + X) ---
    add_ln_kernel<false><<<MTOK, 256>>>(gC, gB, lnw, lnb, (float*)d_out, nullptr, nullptr);
}

// round 13
// speedup vs baseline: 2.7123x; 1.0578x over previous
#include <cuda_runtime.h>
#include <cuda_bf16.h>
#include <stdint.h>

// Problem constants
#define BB 16
#define SS 1024
#define DD 1024
#define HH 16
#define DK 64
#define MTOK (BB*SS)          // 16384 token rows

// Scratch buffers (device globals — no allocation allowed)
__device__ float g_A[(size_t)MTOK * DD];
__device__ float g_B[(size_t)MTOK * DD];
__device__ float g_C[(size_t)MTOK * DD];
// 4 pairs of split-bf16 activation buffers (hi/lo), each MTOK*DD
__device__ __nv_bfloat16 g_bf[(size_t)4 * 2 * MTOK * DD];
// 6 weight pairs (hi/lo), each DD*DD, all stored [N,K]
__device__ __nv_bfloat16 g_w[(size_t)6 * 2 * DD * DD];

// ===========================================================================
// Helpers
// ===========================================================================
__device__ __forceinline__ uint32_t smem_u32(const void* p) {
    uint32_t a;
    asm("{ .reg .u64 t; cvta.to.shared.u64 t, %1; cvt.u32.u64 %0, t; }" : "=r"(a) : "l"(p));
    return a;
}

#define LDSM_X4(R0, R1, R2, R3, addr)                                          \
    asm volatile("ldmatrix.sync.aligned.m8n8.x4.shared.b16 {%0,%1,%2,%3}, [%4];" \
        : "=r"(R0), "=r"(R1), "=r"(R2), "=r"(R3) : "r"(addr))

__device__ __forceinline__ void mma16816(float* d, const uint32_t* a, const uint32_t* b) {
    asm volatile(
        "mma.sync.aligned.m16n8k16.row.col.f32.bf16.bf16.f32 "
        "{%0,%1,%2,%3}, {%4,%5,%6,%7}, {%8,%9}, {%0,%1,%2,%3};"
        : "+f"(d[0]), "+f"(d[1]), "+f"(d[2]), "+f"(d[3])
        : "r"(a[0]), "r"(a[1]), "r"(a[2]), "r"(a[3]), "r"(b[0]), "r"(b[1]));
}

__device__ __forceinline__ void split2(float a, float b, uint32_t& hi, uint32_t& lo) {
    __nv_bfloat16 ah = __float2bfloat16_rn(a);
    __nv_bfloat16 bh = __float2bfloat16_rn(b);
    __nv_bfloat16 al = __float2bfloat16_rn(a - __bfloat162float(ah));
    __nv_bfloat16 bl = __float2bfloat16_rn(b - __bfloat162float(bh));
    hi = (uint32_t)__bfloat16_as_ushort(ah) | ((uint32_t)__bfloat16_as_ushort(bh) << 16);
    lo = (uint32_t)__bfloat16_as_ushort(al) | ((uint32_t)__bfloat16_as_ushort(bl) << 16);
}

#define CP16(sm, gm) asm volatile("cp.async.cg.shared.global [%0], [%1], 16;" :: "r"(sm), "l"(gm))
#define CP_COMMIT()  asm volatile("cp.async.commit_group;")
#define CP_WAIT0()   asm volatile("cp.async.wait_group 0;" ::: "memory")
#define CP_WAIT1()   asm volatile("cp.async.wait_group 1;" ::: "memory")

// ===========================================================================
// Convert kernels (one-time per launch)
// ===========================================================================
__global__ void conv_a(const float* __restrict__ X,
                       __nv_bfloat16* __restrict__ Xh, __nv_bfloat16* __restrict__ Xl)
{
    const size_t i = ((size_t)blockIdx.x * 256 + threadIdx.x) * 4;
    const float4 v = *(const float4*)(X + i);
    uint32_t h0, l0, h1, l1;
    split2(v.x, v.y, h0, l0);
    split2(v.z, v.w, h1, l1);
    *(uint32_t*)(Xh + i)     = h0;  *(uint32_t*)(Xh + i + 2) = h1;
    *(uint32_t*)(Xl + i)     = l0;  *(uint32_t*)(Xl + i + 2) = l1;
}

// W [K,N] fp32 -> Wh/Wl [N,K] bf16 (transpose via smem)
__global__ void conv_w_t(const float* __restrict__ W,
                         __nv_bfloat16* __restrict__ Wh, __nv_bfloat16* __restrict__ Wl)
{
    __shared__ float t[32][33];
    const int n0 = blockIdx.x * 32;
    const int k0 = blockIdx.y * 32;
    const int tx = threadIdx.x, ty = threadIdx.y;
    #pragma unroll
    for (int j = ty; j < 32; j += 8)
        t[j][tx] = W[(size_t)(k0 + j) * DD + n0 + tx];
    __syncthreads();
    const int k = k0 + tx;
    #pragma unroll
    for (int j = ty; j < 32; j += 8) {
        const float v = t[tx][j];
        const __nv_bfloat16 hi = __float2bfloat16_rn(v);
        const __nv_bfloat16 lo = __float2bfloat16_rn(v - __bfloat162float(hi));
        Wh[(size_t)(n0 + j) * DD + k] = hi;
        Wl[(size_t)(n0 + j) * DD + k] = lo;
    }
}

// ===========================================================================
// Split-bf16 mma.sync GEMM: C = A[M,K] @ B^T, pre-split operands.
// CTA 128x128, BK=64, 3-stage cp.async pipeline, term-outer MMA order.
// ===========================================================================
#define RSTRIDE 144                        // bytes per smem row (72 bf16)
#define T_BYTES (128 * RSTRIDE)            // 18432
#define STG_BYTES (4 * T_BYTES)            // 73728
#define GSTAGES 3
#define GEMM_SMEM (GSTAGES * STG_BYTES)    // 221184
#define NCHUNK (DD / 64)                   // 16

template<bool BIAS, bool RELU, bool OUTF32, bool OUTSPLIT>
__global__ void __launch_bounds__(256, 1) mma_gemm(
    const __nv_bfloat16* __restrict__ Ah, const __nv_bfloat16* __restrict__ Al,
    const __nv_bfloat16* __restrict__ Bh, const __nv_bfloat16* __restrict__ Bl,
    const float* __restrict__ bias,
    float* __restrict__ Cf,
    __nv_bfloat16* __restrict__ Ch, __nv_bfloat16* __restrict__ Cl)
{
    extern __shared__ char smem[];
    const uint32_t sbase = smem_u32(smem);
    const int tid  = threadIdx.x;
    const int lane = tid & 31;
    const int wid  = tid >> 5;
    const int wm   = wid & 3;
    const int wn   = wid >> 2;
    const int n0   = blockIdx.x * 128;
    const int m0   = blockIdx.y * 128;

    float acc[2][8][4] = {};

    auto issue = [&](int c, int s) {
        const int k0 = c * 64;
        const uint32_t st = sbase + s * STG_BYTES;
        #pragma unroll
        for (int i = 0; i < 16; i++) {
            const int id   = tid + 256 * i;
            const int tile = id >> 10;                 // 0:Ah 1:Al 2:Bh 3:Bl
            const int w_   = id & 1023;
            const int r    = w_ >> 3;
            const int seg  = w_ & 7;
            const __nv_bfloat16* g =
                (tile == 0 ? Ah : tile == 1 ? Al : tile == 2 ? Bh : Bl)
                + (size_t)((tile < 2 ? m0 : n0) + r) * DD + k0 + seg * 8;
            CP16(st + tile * T_BYTES + r * RSTRIDE + seg * 16, g);
        }
    };

    const int arow   = lane & 15;
    const int acb    = ((lane >> 4) * 8) * 2;
    const int qq     = lane >> 3;
    const int lr     = lane & 7;
    const int brow_q = ((qq & 2) ? 8 : 0) + lr;
    const int bcb    = ((qq & 1) * 8) * 2;

    auto compute = [&](uint32_t stg) {
        const uint32_t sAh = stg;
        const uint32_t sAl = stg + T_BYTES;
        const uint32_t sBh = stg + 2 * T_BYTES;
        const uint32_t sBl = stg + 3 * T_BYTES;
        #pragma unroll
        for (int ks = 0; ks < 4; ks++) {
            const int kb = ks * 32;
            uint32_t ah[2][4], al[2][4], bh[4][4], bl[4][4];
            #pragma unroll
            for (int mt = 0; mt < 2; mt++) {
                const uint32_t off = (uint32_t)((wm * 32 + mt * 16 + arow) * RSTRIDE + kb + acb);
                LDSM_X4(ah[mt][0], ah[mt][1], ah[mt][2], ah[mt][3], sAh + off);
                LDSM_X4(al[mt][0], al[mt][1], al[mt][2], al[mt][3], sAl + off);
            }
            #pragma unroll
            for (int p = 0; p < 4; p++) {
                const uint32_t off = (uint32_t)((wn * 64 + p * 16 + brow_q) * RSTRIDE + kb + bcb);
                LDSM_X4(bh[p][0], bh[p][1], bh[p][2], bh[p][3], sBh + off);
                LDSM_X4(bl[p][0], bl[p][1], bl[p][2], bl[p][3], sBl + off);
            }
            // term-outer: 16 independent accumulators back-to-back per term
            #pragma unroll
            for (int mt = 0; mt < 2; mt++)
                #pragma unroll
                for (int p = 0; p < 4; p++)
                    #pragma unroll
                    for (int h = 0; h < 2; h++)
                        mma16816(acc[mt][p * 2 + h], ah[mt], &bh[p][h * 2]);
            #pragma unroll
            for (int mt = 0; mt < 2; mt++)
                #pragma unroll
                for (int p = 0; p < 4; p++)
                    #pragma unroll
                    for (int h = 0; h < 2; h++)
                        mma16816(acc[mt][p * 2 + h], ah[mt], &bl[p][h * 2]);
            #pragma unroll
            for (int mt = 0; mt < 2; mt++)
                #pragma unroll
                for (int p = 0; p < 4; p++)
                    #pragma unroll
                    for (int h = 0; h < 2; h++)
                        mma16816(acc[mt][p * 2 + h], al[mt], &bh[p][h * 2]);
        }
    };

    // 3-stage pipeline: 2 chunks in flight
    issue(0, 0); CP_COMMIT();
    issue(1, 1); CP_COMMIT();
    for (int c = 0; c < NCHUNK; c++) {
        CP_WAIT1();            // oldest outstanding group (chunk c) arrived
        __syncthreads();
        if (c + 2 < NCHUNK) issue(c + 2, (c + 2) % 3);
        CP_COMMIT();           // empty commit keeps accounting exact
        compute(sbase + (c % 3) * STG_BYTES);
    }

    // Epilogue
    #pragma unroll
    for (int mt = 0; mt < 2; mt++) {
        const int row = m0 + wm * 32 + mt * 16 + (lane >> 2);
        #pragma unroll
        for (int nt = 0; nt < 8; nt++) {
            const int col = n0 + wn * 64 + nt * 8 + (lane & 3) * 2;
            float b0 = 0.f, b1 = 0.f;
            if (BIAS) { b0 = __ldg(bias + col); b1 = __ldg(bias + col + 1); }
            float2 v01, v23;
            v01.x = acc[mt][nt][0] + b0;  v01.y = acc[mt][nt][1] + b1;
            v23.x = acc[mt][nt][2] + b0;  v23.y = acc[mt][nt][3] + b1;
            if (RELU) {
                v01.x = fmaxf(v01.x, 0.f); v01.y = fmaxf(v01.y, 0.f);
                v23.x = fmaxf(v23.x, 0.f); v23.y = fmaxf(v23.y, 0.f);
            }
            if (OUTF32) {
                *(float2*)(Cf + (size_t)row * DD + col)       = v01;
                *(float2*)(Cf + (size_t)(row + 8) * DD + col) = v23;
            }
            if (OUTSPLIT) {
                uint32_t h, l;
                split2(v01.x, v01.y, h, l);
                *(uint32_t*)(Ch + (size_t)row * DD + col) = h;
                *(uint32_t*)(Cl + (size_t)row * DD + col) = l;
                split2(v23.x, v23.y, h, l);
                *(uint32_t*)(Ch + (size_t)(row + 8) * DD + col) = h;
                *(uint32_t*)(Cl + (size_t)(row + 8) * DD + col) = l;
            }
        }
    }
}

// ===========================================================================
// Tensor-core flash attention, pre-split bf16 inputs, double-buffered K/V,
// Q fragments hoisted out of the kt loop, term-outer MMA order.
// ===========================================================================
#define AST 72
#define QTILE_B (128 * AST * 2)            // 18432
#define KTILE_B (64 * AST * 2)             // 9216
#define KVSTG (4 * KTILE_B)                // 36864
#define ATT_SMEM (2 * QTILE_B + 2 * KVSTG) // 110592

__global__ void __launch_bounds__(256) attn_mma_kernel(
    const __nv_bfloat16* __restrict__ Qh_, const __nv_bfloat16* __restrict__ Ql_,
    const __nv_bfloat16* __restrict__ Kh_, const __nv_bfloat16* __restrict__ Kl_,
    const __nv_bfloat16* __restrict__ Vh_, const __nv_bfloat16* __restrict__ Vl_,
    const unsigned char* __restrict__ mask,
    __nv_bfloat16* __restrict__ Ch, __nv_bfloat16* __restrict__ Cl)
{
    extern __shared__ char sm[];
    const uint32_t sb = smem_u32(sm);
    const int tid  = threadIdx.x;
    const int lane = tid & 31;
    const int w    = tid >> 5;
    const int qt   = blockIdx.x;           // 0..7
    const int bh   = blockIdx.y;
    const int b    = bh >> 4;
    const int h    = bh & 15;

    const uint32_t uQh = sb;
    const uint32_t uQl = sb + QTILE_B;
    const uint32_t kvBase = sb + 2 * QTILE_B;

    const size_t base = (size_t)b * SS * DD + (size_t)h * DK;

    // ---- Q tile cp.async ----
    #pragma unroll
    for (int i = 0; i < 8; i++) {
        const int id   = tid + 256 * i;
        const int tile = id >> 10;
        const int r    = (id >> 3) & 127;
        const int seg  = id & 7;
        const __nv_bfloat16* g = (tile ? Ql_ : Qh_)
            + base + (size_t)(qt * 128 + r) * DD + seg * 8;
        CP16(sb + tile * QTILE_B + r * 144 + seg * 16, g);
    }
    CP_COMMIT();

    auto issueK = [&](int kt, int s) {
        const uint32_t st = kvBase + s * KVSTG;
        #pragma unroll
        for (int i = 0; i < 4; i++) {
            const int id   = tid + 256 * i;
            const int tile = id >> 9;          // 0 hi, 1 lo
            const int r    = (id >> 3) & 63;
            const int seg  = id & 7;
            const __nv_bfloat16* g = (tile ? Kl_ : Kh_)
                + base + (size_t)(kt * 64 + r) * DD + seg * 8;
            CP16(st + tile * KTILE_B + r * 144 + seg * 16, g);
        }
    };

    const int vrow = (tid & 31) * 2;
    const int dblk = tid >> 5;
    uint4 vh0, vh1, vl0, vl1;
    auto ldgV = [&](int kt) {
        const __nv_bfloat16* gh = Vh_ + base + (size_t)(kt * 64 + vrow) * DD + dblk * 8;
        const __nv_bfloat16* gl = Vl_ + base + (size_t)(kt * 64 + vrow) * DD + dblk * 8;
        vh0 = *(const uint4*)gh;  vh1 = *(const uint4*)(gh + DD);
        vl0 = *(const uint4*)gl;  vl1 = *(const uint4*)(gl + DD);
    };
    auto stsV = [&](int s) {
        const uint32_t st = kvBase + s * KVSTG;
        const uint16_t* h0p = (const uint16_t*)&vh0;
        const uint16_t* h1p = (const uint16_t*)&vh1;
        const uint16_t* l0p = (const uint16_t*)&vl0;
        const uint16_t* l1p = (const uint16_t*)&vl1;
        #pragma unroll
        for (int d = 0; d < 8; d++) {
            const uint32_t off = (uint32_t)((dblk * 8 + d) * 144 + vrow * 2);
            *(uint32_t*)(sm + (st - sb) + 2 * KTILE_B + off) =
                (uint32_t)h0p[d] | ((uint32_t)h1p[d] << 16);
            *(uint32_t*)(sm + (st - sb) + 3 * KTILE_B + off) =
                (uint32_t)l0p[d] | ((uint32_t)l1p[d] << 16);
        }
    };

    const int r0 = lane >> 2;
    unsigned char pm[2];
    pm[0] = mask[(size_t)b * SS + qt * 128 + w * 16 + r0];
    pm[1] = mask[(size_t)b * SS + qt * 128 + w * 16 + r0 + 8];

    float m_r[2] = {-1e30f, -1e30f};
    float l_r[2] = {0.f, 0.f};
    float acc_o[8][4] = {};

    const float NEGV  = -4294967295.0f;
    const float scale = 1.0f / 8.000001f;

    const int arow   = lane & 15;
    const int acb    = ((lane >> 4) * 8) * 2;
    const int qq     = lane >> 3;
    const int lr     = lane & 7;
    const int brow_q = ((qq & 2) ? 8 : 0) + lr;
    const int bcb    = ((qq & 1) * 8) * 2;

    // ---- prologue: K(0) + V(0) ----
    issueK(0, 0); CP_COMMIT();
    ldgV(0);
    CP_WAIT0();
    __syncthreads();       // Q, K0 visible
    stsV(0);

    // ---- hoist Q fragments (kt-invariant) ----
    uint32_t qfh[4][4], qfl[4][4];
    #pragma unroll
    for (int ks = 0; ks < 4; ks++) {
        const uint32_t off = (uint32_t)((w * 16 + arow) * 144 + ks * 32 + acb);
        LDSM_X4(qfh[ks][0], qfh[ks][1], qfh[ks][2], qfh[ks][3], uQh + off);
        LDSM_X4(qfl[ks][0], qfl[ks][1], qfl[ks][2], qfl[ks][3], uQl + off);
    }
    __syncthreads();       // V0 visible

    const int kmax = 2 * qt + 1;
    for (int kt = 0; kt <= kmax; kt++) {
        const int s = kt & 1;
        const uint32_t st = kvBase + s * KVSTG;
        const uint32_t uKh = st;
        const uint32_t uKl = st + KTILE_B;
        const uint32_t uVh = st + 2 * KTILE_B;
        const uint32_t uVl = st + 3 * KTILE_B;

        if (kt < kmax) {
            issueK(kt + 1, s ^ 1); CP_COMMIT();
            ldgV(kt + 1);
        }

        // ---- scores S = Q @ K^T (term-outer) ----
        float sc[8][4] = {};
        #pragma unroll
        for (int ks = 0; ks < 4; ks++) {
            const int kb = ks * 32;
            uint32_t kh[4][4], kl[4][4];
            #pragma unroll
            for (int p = 0; p < 4; p++) {
                const uint32_t off = (uint32_t)((p * 16 + brow_q) * 144 + kb + bcb);
                LDSM_X4(kh[p][0], kh[p][1], kh[p][2], kh[p][3], uKh + off);
                LDSM_X4(kl[p][0], kl[p][1], kl[p][2], kl[p][3], uKl + off);
            }
            #pragma unroll
            for (int p = 0; p < 4; p++)
                #pragma unroll
                for (int hh = 0; hh < 2; hh++)
                    mma16816(sc[p * 2 + hh], qfh[ks], &kh[p][hh * 2]);
            #pragma unroll
            for (int p = 0; p < 4; p++)
                #pragma unroll
                for (int hh = 0; hh < 2; hh++)
                    mma16816(sc[p * 2 + hh], qfh[ks], &kl[p][hh * 2]);
            #pragma unroll
            for (int p = 0; p < 4; p++)
                #pragma unroll
                for (int hh = 0; hh < 2; hh++)
                    mma16816(sc[p * 2 + hh], qfl[ks], &kh[p][hh * 2]);
        }

        // ---- scale + causal/pad mask ----
        const int qg0 = qt * 128 + w * 16 + r0;
        #pragma unroll
        for (int nt = 0; nt < 8; nt++) {
            const int cg = kt * 64 + nt * 8 + (lane & 3) * 2;
            #pragma unroll
            for (int j = 0; j < 4; j++) {
                const int row_g = (j >> 1) ? qg0 + 8 : qg0;
                const int col_g = cg + (j & 1);
                sc[nt][j] *= scale;
                if (col_g > row_g || pm[j >> 1]) sc[nt][j] = NEGV;
            }
        }

        // ---- online softmax ----
        #pragma unroll
        for (int half = 0; half < 2; half++) {
            float tm = -1e30f;
            #pragma unroll
            for (int nt = 0; nt < 8; nt++)
                tm = fmaxf(tm, fmaxf(sc[nt][half * 2], sc[nt][half * 2 + 1]));
            tm = fmaxf(tm, __shfl_xor_sync(0xffffffffu, tm, 1));
            tm = fmaxf(tm, __shfl_xor_sync(0xffffffffu, tm, 2));
            const float mn = fmaxf(m_r[half], tm);
            const float f = __expf(m_r[half] - mn);
            float ps = 0.f;
            #pragma unroll
            for (int nt = 0; nt < 8; nt++) {
                const float p0 = __expf(sc[nt][half * 2]     - mn);
                const float p1 = __expf(sc[nt][half * 2 + 1] - mn);
                sc[nt][half * 2]     = p0;
                sc[nt][half * 2 + 1] = p1;
                ps += p0 + p1;
                acc_o[nt][half * 2]     *= f;
                acc_o[nt][half * 2 + 1] *= f;
            }
            ps += __shfl_xor_sync(0xffffffffu, ps, 1);
            ps += __shfl_xor_sync(0xffffffffu, ps, 2);
            l_r[half] = l_r[half] * f + ps;
            m_r[half] = mn;
        }

        // store next V into the spare stage
        if (kt < kmax) stsV(s ^ 1);

        // ---- O += P @ V (term-outer) ----
        #pragma unroll
        for (int ks = 0; ks < 4; ks++) {
            uint32_t ph[4], pl[4];
            const int t0 = 2 * ks, t1 = 2 * ks + 1;
            split2(sc[t0][0], sc[t0][1], ph[0], pl[0]);
            split2(sc[t0][2], sc[t0][3], ph[1], pl[1]);
            split2(sc[t1][0], sc[t1][1], ph[2], pl[2]);
            split2(sc[t1][2], sc[t1][3], ph[3], pl[3]);

            const int kb = ks * 32;
            uint32_t vh[4][4], vl[4][4];
            #pragma unroll
            for (int p = 0; p < 4; p++) {
                const uint32_t off = (uint32_t)((p * 16 + brow_q) * 144 + kb + bcb);
                LDSM_X4(vh[p][0], vh[p][1], vh[p][2], vh[p][3], uVh + off);
                LDSM_X4(vl[p][0], vl[p][1], vl[p][2], vl[p][3], uVl + off);
            }
            #pragma unroll
            for (int p = 0; p < 4; p++)
                #pragma unroll
                for (int hh = 0; hh < 2; hh++)
                    mma16816(acc_o[p * 2 + hh], ph, &vh[p][hh * 2]);
            #pragma unroll
            for (int p = 0; p < 4; p++)
                #pragma unroll
                for (int hh = 0; hh < 2; hh++)
                    mma16816(acc_o[p * 2 + hh], ph, &vl[p][hh * 2]);
            #pragma unroll
            for (int p = 0; p < 4; p++)
                #pragma unroll
                for (int hh = 0; hh < 2; hh++)
                    mma16816(acc_o[p * 2 + hh], pl, &vh[p][hh * 2]);
        }

        if (kt < kmax) {
            CP_WAIT0();
            __syncthreads();
        }
    }

    // ---- normalize + write split ctx ----
    const float inv0 = 1.0f / l_r[0];
    const float inv1 = 1.0f / l_r[1];
    const int row0 = qt * 128 + w * 16 + r0;
    #pragma unroll
    for (int nt = 0; nt < 8; nt++) {
        const int col = h * DK + nt * 8 + (lane & 3) * 2;
        uint32_t hh, ll;
        split2(acc_o[nt][0] * inv0, acc_o[nt][1] * inv0, hh, ll);
        *(uint32_t*)(Ch + ((size_t)b * SS + row0) * DD + col) = hh;
        *(uint32_t*)(Cl + ((size_t)b * SS + row0) * DD + col) = ll;
        split2(acc_o[nt][2] * inv1, acc_o[nt][3] * inv1, hh, ll);
        *(uint32_t*)(Ch + ((size_t)b * SS + row0 + 8) * DD + col) = hh;
        *(uint32_t*)(Cl + ((size_t)b * SS + row0 + 8) * DD + col) = ll;
    }
}

// ---------------------------------------------------------------------------
// out = LayerNorm(X + R) * w + b ; optional split-bf16 copy of out
// ---------------------------------------------------------------------------
template<bool SPLIT>
__global__ void __launch_bounds__(256) add_ln_kernel(
    const float* __restrict__ X, const float* __restrict__ R,
    const float* __restrict__ w, const float* __restrict__ bb,
    float* __restrict__ out,
    __nv_bfloat16* __restrict__ Oh, __nv_bfloat16* __restrict__ Ol)
{
    const int row = blockIdx.x;
    const int tid = threadIdx.x;
    const float4* x4 = (const float4*)(X + (size_t)row * DD);
    const float4* r4 = (const float4*)(R + (size_t)row * DD);
    float4 v = x4[tid];
    const float4 r = r4[tid];
    v.x += r.x; v.y += r.y; v.z += r.z; v.w += r.w;

    float sum = v.x + v.y + v.z + v.w;
    float sq  = v.x*v.x + v.y*v.y + v.z*v.z + v.w*v.w;
    #pragma unroll
    for (int off = 16; off; off >>= 1) {
        sum += __shfl_xor_sync(0xffffffffu, sum, off);
        sq  += __shfl_xor_sync(0xffffffffu, sq, off);
    }
    __shared__ float ssum[8], ssq[8];
    if ((tid & 31) == 0) { ssum[tid >> 5] = sum; ssq[tid >> 5] = sq; }
    __syncthreads();
    float tot = 0.f, totq = 0.f;
    #pragma unroll
    for (int i = 0; i < 8; i++) { tot += ssum[i]; totq += ssq[i]; }
    const float mu   = tot * (1.0f / DD);
    const float var  = totq * (1.0f / DD) - mu * mu;
    const float rstd = rsqrtf(var + 1e-5f);

    const float4 wv = ((const float4*)w)[tid];
    const float4 bv = ((const float4*)bb)[tid];
    float4 ov;
    ov.x = (v.x - mu) * rstd * wv.x + bv.x;
    ov.y = (v.y - mu) * rstd * wv.y + bv.y;
    ov.z = (v.z - mu) * rstd * wv.z + bv.z;
    ov.w = (v.w - mu) * rstd * wv.w + bv.w;
    ((float4*)(out + (size_t)row * DD))[tid] = ov;
    if (SPLIT) {
        uint32_t h0, l0, h1, l1;
        split2(ov.x, ov.y, h0, l0);
        split2(ov.z, ov.w, h1, l1);
        const size_t o = (size_t)row * DD + tid * 4;
        *(uint32_t*)(Oh + o)     = h0;  *(uint32_t*)(Oh + o + 2) = h1;
        *(uint32_t*)(Ol + o)     = l0;  *(uint32_t*)(Ol + o + 2) = l1;
    }
}

// ---------------------------------------------------------------------------
extern "C" void kernel_launch(void* const* d_in, const int* in_sizes, int n_in,
                              void* d_out, int out_size)
{
    int mi = -1;
    for (int i = 0; i < n_in; i++)
        if (in_sizes[i] == BB * SS) { mi = i; break; }

    const float *Q, *K, *V, *Wq, *Wk, *Wv, *Wo, *l1w, *l1b, *l2w, *l2b, *lnw, *lnb;
    const unsigned char* mask;
    if (mi == 3) {
        Q   = (const float*)d_in[0];  K   = (const float*)d_in[1];
        V   = (const float*)d_in[2];  mask = (const unsigned char*)d_in[3];
        Wq  = (const float*)d_in[4];  Wk  = (const float*)d_in[5];
        Wv  = (const float*)d_in[6];  Wo  = (const float*)d_in[7];
        l1w = (const float*)d_in[8];  l1b = (const float*)d_in[9];
        l2w = (const float*)d_in[10]; l2b = (const float*)d_in[11];
        lnw = (const float*)d_in[12]; lnb = (const float*)d_in[13];
    } else {
        Q   = (const float*)d_in[0];  K   = (const float*)d_in[1];
        V   = (const float*)d_in[2];
        Wq  = (const float*)d_in[3];  Wk  = (const float*)d_in[4];
        Wv  = (const float*)d_in[5];  Wo  = (const float*)d_in[6];
        l1w = (const float*)d_in[7];  l1b = (const float*)d_in[8];
        l2w = (const float*)d_in[9];  l2b = (const float*)d_in[10];
        lnw = (const float*)d_in[11]; lnb = (const float*)d_in[12];
        mask = (const unsigned char*)d_in[13];
    }

    float *gA, *gB, *gC;
    __nv_bfloat16 *bf, *wsp;
    cudaGetSymbolAddress((void**)&gA, g_A);
    cudaGetSymbolAddress((void**)&gB, g_B);
    cudaGetSymbolAddress((void**)&gC, g_C);
    cudaGetSymbolAddress((void**)&bf, g_bf);
    cudaGetSymbolAddress((void**)&wsp, g_w);

    const size_t PSZ = (size_t)MTOK * DD;
    auto P = [&](int i, int half) { return bf + ((size_t)(i * 2 + half)) * PSZ; };
    const size_t WSZ = (size_t)DD * DD;
    auto W = [&](int i, int half) { return wsp + ((size_t)(i * 2 + half)) * WSZ; };

    cudaFuncSetAttribute(mma_gemm<false, false, false, true>,
                         cudaFuncAttributeMaxDynamicSharedMemorySize, GEMM_SMEM);
    cudaFuncSetAttribute(mma_gemm<false, false, true, false>,
                         cudaFuncAttributeMaxDynamicSharedMemorySize, GEMM_SMEM);
    cudaFuncSetAttribute(mma_gemm<true, true, false, true>,
                         cudaFuncAttributeMaxDynamicSharedMemorySize, GEMM_SMEM);
    cudaFuncSetAttribute(mma_gemm<true, false, true, false>,
                         cudaFuncAttributeMaxDynamicSharedMemorySize, GEMM_SMEM);
    cudaFuncSetAttribute(attn_mma_kernel,
                         cudaFuncAttributeMaxDynamicSharedMemorySize, ATT_SMEM);

    // --- converts ---
    const dim3 wtGrid(DD / 32, DD / 32);
    conv_w_t<<<wtGrid, dim3(32, 8)>>>(Wq, W(0,0), W(0,1));
    conv_w_t<<<wtGrid, dim3(32, 8)>>>(Wk, W(1,0), W(1,1));
    conv_w_t<<<wtGrid, dim3(32, 8)>>>(Wv, W(2,0), W(2,1));
    conv_w_t<<<wtGrid, dim3(32, 8)>>>(Wo, W(3,0), W(3,1));
    conv_a<<<(int)(WSZ / 1024), 256>>>(l1w, W(4,0), W(4,1));
    conv_a<<<(int)(WSZ / 1024), 256>>>(l2w, W(5,0), W(5,1));
    conv_a<<<(int)(PSZ / 1024), 256>>>(Q, P(0,0), P(0,1));
    conv_a<<<(int)(PSZ / 1024), 256>>>(K, P(1,0), P(1,1));
    conv_a<<<(int)(PSZ / 1024), 256>>>(V, P(2,0), P(2,1));

    const dim3 gGrid(DD / 128, MTOK / 128);   // (8, 128)

    // --- QKV projections -> split outputs ---
    mma_gemm<false, false, false, true><<<gGrid, 256, GEMM_SMEM>>>(
        P(0,0), P(0,1), W(0,0), W(0,1), nullptr, nullptr, P(3,0), P(3,1));   // Qp
    mma_gemm<false, false, false, true><<<gGrid, 256, GEMM_SMEM>>>(
        P(1,0), P(1,1), W(1,0), W(1,1), nullptr, nullptr, P(0,0), P(0,1));   // Kp
    mma_gemm<false, false, false, true><<<gGrid, 256, GEMM_SMEM>>>(
        P(2,0), P(2,1), W(2,0), W(2,1), nullptr, nullptr, P(1,0), P(1,1));   // Vp

    // --- attention -> split ctx ---
    attn_mma_kernel<<<dim3(SS / 128, BB * HH), 256, ATT_SMEM>>>(
        P(3,0), P(3,1), P(0,0), P(0,1), P(1,0), P(1,1), mask, P(2,0), P(2,1));

    // --- output projection -> fp32 ---
    mma_gemm<false, false, true, false><<<gGrid, 256, GEMM_SMEM>>>(
        P(2,0), P(2,1), W(3,0), W(3,1), nullptr, gA, nullptr, nullptr);

    // --- X = LN(V_att + Q): fp32 + splits ---
    add_ln_kernel<true><<<MTOK, 256>>>(gA, Q, lnw, lnb, gB, P(3,0), P(3,1));

    // --- FFN ---
    mma_gemm<true, true, false, true><<<gGrid, 256, GEMM_SMEM>>>(
        P(3,0), P(3,1), W(4,0), W(4,1), l1b, nullptr, P(0,0), P(0,1));
    mma_gemm<true, false, true, false><<<gGrid, 256, GEMM_SMEM>>>(
        P(0,0), P(0,1), W(5,0), W(5,1), l2b, gC, nullptr, nullptr);

    // --- out = LN(ffn + X) ---
    add_ln_kernel<false><<<MTOK, 256>>>(gC, gB, lnw, lnb, (float*)d_out, nullptr, nullptr);
}

// round 15
// speedup vs baseline: 2.7137x; 1.0005x over previous
#include <cuda_runtime.h>
#include <cuda_bf16.h>
#include <stdint.h>

// Problem constants
#define BB 16
#define SS 1024
#define DD 1024
#define HH 16
#define DK 64
#define MTOK (BB*SS)          // 16384 token rows

// Scratch buffers (device globals — no allocation allowed)
__device__ float g_A[(size_t)MTOK * DD];
__device__ float g_B[(size_t)MTOK * DD];
__device__ float g_C[(size_t)MTOK * DD];
// 4 pairs of split-bf16 activation buffers (hi/lo), each MTOK*DD
__device__ __nv_bfloat16 g_bf[(size_t)4 * 2 * MTOK * DD];
// 6 weight pairs (hi/lo), each DD*DD, all stored [N,K]
__device__ __nv_bfloat16 g_w[(size_t)6 * 2 * DD * DD];

// ===========================================================================
// Helpers
// ===========================================================================
__device__ __forceinline__ uint32_t smem_u32(const void* p) {
    uint32_t a;
    asm("{ .reg .u64 t; cvta.to.shared.u64 t, %1; cvt.u32.u64 %0, t; }" : "=r"(a) : "l"(p));
    return a;
}

#define LDSM_X4(R0, R1, R2, R3, addr)                                          \
    asm volatile("ldmatrix.sync.aligned.m8n8.x4.shared.b16 {%0,%1,%2,%3}, [%4];" \
        : "=r"(R0), "=r"(R1), "=r"(R2), "=r"(R3) : "r"(addr))

__device__ __forceinline__ void mma16816(float* d, const uint32_t* a, const uint32_t* b) {
    asm volatile(
        "mma.sync.aligned.m16n8k16.row.col.f32.bf16.bf16.f32 "
        "{%0,%1,%2,%3}, {%4,%5,%6,%7}, {%8,%9}, {%0,%1,%2,%3};"
        : "+f"(d[0]), "+f"(d[1]), "+f"(d[2]), "+f"(d[3])
        : "r"(a[0]), "r"(a[1]), "r"(a[2]), "r"(a[3]), "r"(b[0]), "r"(b[1]));
}

__device__ __forceinline__ void split2(float a, float b, uint32_t& hi, uint32_t& lo) {
    __nv_bfloat16 ah = __float2bfloat16_rn(a);
    __nv_bfloat16 bh = __float2bfloat16_rn(b);
    __nv_bfloat16 al = __float2bfloat16_rn(a - __bfloat162float(ah));
    __nv_bfloat16 bl = __float2bfloat16_rn(b - __bfloat162float(bh));
    hi = (uint32_t)__bfloat16_as_ushort(ah) | ((uint32_t)__bfloat16_as_ushort(bh) << 16);
    lo = (uint32_t)__bfloat16_as_ushort(al) | ((uint32_t)__bfloat16_as_ushort(bl) << 16);
}

#define CP16(sm, gm) asm volatile("cp.async.cg.shared.global [%0], [%1], 16;" :: "r"(sm), "l"(gm))
#define CP_COMMIT()  asm volatile("cp.async.commit_group;")
#define CP_WAIT0()   asm volatile("cp.async.wait_group 0;" ::: "memory")
#define CP_WAIT1()   asm volatile("cp.async.wait_group 1;" ::: "memory")

// ===========================================================================
// Convert kernels (one-time per launch)
// ===========================================================================
__global__ void conv_a(const float* __restrict__ X,
                       __nv_bfloat16* __restrict__ Xh, __nv_bfloat16* __restrict__ Xl)
{
    const size_t i = ((size_t)blockIdx.x * 256 + threadIdx.x) * 4;
    const float4 v = *(const float4*)(X + i);
    uint32_t h0, l0, h1, l1;
    split2(v.x, v.y, h0, l0);
    split2(v.z, v.w, h1, l1);
    *(uint32_t*)(Xh + i)     = h0;  *(uint32_t*)(Xh + i + 2) = h1;
    *(uint32_t*)(Xl + i)     = l0;  *(uint32_t*)(Xl + i + 2) = l1;
}

// W [K,N] fp32 -> Wh/Wl [N,K] bf16 (transpose via smem)
__global__ void conv_w_t(const float* __restrict__ W,
                         __nv_bfloat16* __restrict__ Wh, __nv_bfloat16* __restrict__ Wl)
{
    __shared__ float t[32][33];
    const int n0 = blockIdx.x * 32;
    const int k0 = blockIdx.y * 32;
    const int tx = threadIdx.x, ty = threadIdx.y;
    #pragma unroll
    for (int j = ty; j < 32; j += 8)
        t[j][tx] = W[(size_t)(k0 + j) * DD + n0 + tx];
    __syncthreads();
    const int k = k0 + tx;
    #pragma unroll
    for (int j = ty; j < 32; j += 8) {
        const float v = t[tx][j];
        const __nv_bfloat16 hi = __float2bfloat16_rn(v);
        const __nv_bfloat16 lo = __float2bfloat16_rn(v - __bfloat162float(hi));
        Wh[(size_t)(n0 + j) * DD + k] = hi;
        Wl[(size_t)(n0 + j) * DD + k] = lo;
    }
}

// ===========================================================================
// Split-bf16 mma.sync GEMM: C = A[M,K] @ B^T, pre-split operands.
// CTA 128x128, 512 threads / 16 warps (4x4), warp tile 32x32.
// BK=64, 3-stage cp.async pipeline, term-outer MMA order.
// ===========================================================================
#define RSTRIDE 144                        // bytes per smem row (72 bf16)
#define T_BYTES (128 * RSTRIDE)            // 18432
#define STG_BYTES (4 * T_BYTES)            // 73728
#define GSTAGES 3
#define GEMM_SMEM (GSTAGES * STG_BYTES)    // 221184
#define NCHUNK (DD / 64)                   // 16

template<bool BIAS, bool RELU, bool OUTF32, bool OUTSPLIT>
__global__ void __launch_bounds__(512, 1) mma_gemm(
    const __nv_bfloat16* __restrict__ Ah, const __nv_bfloat16* __restrict__ Al,
    const __nv_bfloat16* __restrict__ Bh, const __nv_bfloat16* __restrict__ Bl,
    const float* __restrict__ bias,
    float* __restrict__ Cf,
    __nv_bfloat16* __restrict__ Ch, __nv_bfloat16* __restrict__ Cl)
{
    extern __shared__ char smem[];
    const uint32_t sbase = smem_u32(smem);
    const int tid  = threadIdx.x;
    const int lane = tid & 31;
    const int wid  = tid >> 5;           // 0..15
    const int wm   = wid & 3;            // 4 m-warps * 32 rows
    const int wn   = wid >> 2;           // 4 n-warps * 32 cols
    const int n0   = blockIdx.x * 128;
    const int m0   = blockIdx.y * 128;

    float acc[2][4][4] = {};             // [mt][n8][4]

    auto issue = [&](int c, int s) {
        const int k0 = c * 64;
        const uint32_t st = sbase + s * STG_BYTES;
        #pragma unroll
        for (int i = 0; i < 8; i++) {
            const int id   = tid + 512 * i;
            const int tile = id >> 10;                 // 0:Ah 1:Al 2:Bh 3:Bl
            const int w_   = id & 1023;
            const int r    = w_ >> 3;
            const int seg  = w_ & 7;
            const __nv_bfloat16* g =
                (tile == 0 ? Ah : tile == 1 ? Al : tile == 2 ? Bh : Bl)
                + (size_t)((tile < 2 ? m0 : n0) + r) * DD + k0 + seg * 8;
            CP16(st + tile * T_BYTES + r * RSTRIDE + seg * 16, g);
        }
    };

    const int arow   = lane & 15;
    const int acb    = ((lane >> 4) * 8) * 2;
    const int qq     = lane >> 3;
    const int lr     = lane & 7;
    const int brow_q = ((qq & 2) ? 8 : 0) + lr;
    const int bcb    = ((qq & 1) * 8) * 2;

    auto compute = [&](uint32_t stg) {
        const uint32_t sAh = stg;
        const uint32_t sAl = stg + T_BYTES;
        const uint32_t sBh = stg + 2 * T_BYTES;
        const uint32_t sBl = stg + 3 * T_BYTES;
        #pragma unroll
        for (int ks = 0; ks < 4; ks++) {
            const int kb = ks * 32;
            uint32_t ah[2][4], al[2][4], bh[2][4], bl[2][4];
            #pragma unroll
            for (int mt = 0; mt < 2; mt++) {
                const uint32_t off = (uint32_t)((wm * 32 + mt * 16 + arow) * RSTRIDE + kb + acb);
                LDSM_X4(ah[mt][0], ah[mt][1], ah[mt][2], ah[mt][3], sAh + off);
                LDSM_X4(al[mt][0], al[mt][1], al[mt][2], al[mt][3], sAl + off);
            }
            #pragma unroll
            for (int p = 0; p < 2; p++) {
                const uint32_t off = (uint32_t)((wn * 32 + p * 16 + brow_q) * RSTRIDE + kb + bcb);
                LDSM_X4(bh[p][0], bh[p][1], bh[p][2], bh[p][3], sBh + off);
                LDSM_X4(bl[p][0], bl[p][1], bl[p][2], bl[p][3], sBl + off);
            }
            // term-outer: 8 independent accumulators back-to-back per term
            #pragma unroll
            for (int mt = 0; mt < 2; mt++)
                #pragma unroll
                for (int p = 0; p < 2; p++)
                    #pragma unroll
                    for (int h = 0; h < 2; h++)
                        mma16816(acc[mt][p * 2 + h], ah[mt], &bh[p][h * 2]);
            #pragma unroll
            for (int mt = 0; mt < 2; mt++)
                #pragma unroll
                for (int p = 0; p < 2; p++)
                    #pragma unroll
                    for (int h = 0; h < 2; h++)
                        mma16816(acc[mt][p * 2 + h], ah[mt], &bl[p][h * 2]);
            #pragma unroll
            for (int mt = 0; mt < 2; mt++)
                #pragma unroll
                for (int p = 0; p < 2; p++)
                    #pragma unroll
                    for (int h = 0; h < 2; h++)
                        mma16816(acc[mt][p * 2 + h], al[mt], &bh[p][h * 2]);
        }
    };

    // 3-stage pipeline: 2 chunks in flight
    issue(0, 0); CP_COMMIT();
    issue(1, 1); CP_COMMIT();
    for (int c = 0; c < NCHUNK; c++) {
        CP_WAIT1();            // oldest outstanding group (chunk c) arrived
        __syncthreads();
        if (c + 2 < NCHUNK) issue(c + 2, (c + 2) % 3);
        CP_COMMIT();           // empty commit keeps accounting exact
        compute(sbase + (c % 3) * STG_BYTES);
    }

    // Epilogue: warp tile 32x32 at (wm*32, wn*32)
    #pragma unroll
    for (int mt = 0; mt < 2; mt++) {
        const int row = m0 + wm * 32 + mt * 16 + (lane >> 2);
        #pragma unroll
        for (int nt = 0; nt < 4; nt++) {
            const int col = n0 + wn * 32 + nt * 8 + (lane & 3) * 2;
            float b0 = 0.f, b1 = 0.f;
            if (BIAS) { b0 = __ldg(bias + col); b1 = __ldg(bias + col + 1); }
            float2 v01, v23;
            v01.x = acc[mt][nt][0] + b0;  v01.y = acc[mt][nt][1] + b1;
            v23.x = acc[mt][nt][2] + b0;  v23.y = acc[mt][nt][3] + b1;
            if (RELU) {
                v01.x = fmaxf(v01.x, 0.f); v01.y = fmaxf(v01.y, 0.f);
                v23.x = fmaxf(v23.x, 0.f); v23.y = fmaxf(v23.y, 0.f);
            }
            if (OUTF32) {
                *(float2*)(Cf + (size_t)row * DD + col)       = v01;
                *(float2*)(Cf + (size_t)(row + 8) * DD + col) = v23;
            }
            if (OUTSPLIT) {
                uint32_t h, l;
                split2(v01.x, v01.y, h, l);
                *(uint32_t*)(Ch + (size_t)row * DD + col) = h;
                *(uint32_t*)(Cl + (size_t)row * DD + col) = l;
                split2(v23.x, v23.y, h, l);
                *(uint32_t*)(Ch + (size_t)(row + 8) * DD + col) = h;
                *(uint32_t*)(Cl + (size_t)(row + 8) * DD + col) = l;
            }
        }
    }
}

// ===========================================================================
// Tensor-core flash attention, pre-split bf16 inputs, double-buffered K/V,
// Q fragments hoisted out of the kt loop, term-outer MMA order.
// ===========================================================================
#define AST 72
#define QTILE_B (128 * AST * 2)            // 18432
#define KTILE_B (64 * AST * 2)             // 9216
#define KVSTG (4 * KTILE_B)                // 36864
#define ATT_SMEM (2 * QTILE_B + 2 * KVSTG) // 110592

__global__ void __launch_bounds__(256) attn_mma_kernel(
    const __nv_bfloat16* __restrict__ Qh_, const __nv_bfloat16* __restrict__ Ql_,
    const __nv_bfloat16* __restrict__ Kh_, const __nv_bfloat16* __restrict__ Kl_,
    const __nv_bfloat16* __restrict__ Vh_, const __nv_bfloat16* __restrict__ Vl_,
    const unsigned char* __restrict__ mask,
    __nv_bfloat16* __restrict__ Ch, __nv_bfloat16* __restrict__ Cl)
{
    extern __shared__ char sm[];
    const uint32_t sb = smem_u32(sm);
    const int tid  = threadIdx.x;
    const int lane = tid & 31;
    const int w    = tid >> 5;
    const int qt   = blockIdx.x;           // 0..7
    const int bh   = blockIdx.y;
    const int b    = bh >> 4;
    const int h    = bh & 15;

    const uint32_t uQh = sb;
    const uint32_t uQl = sb + QTILE_B;
    const uint32_t kvBase = sb + 2 * QTILE_B;

    const size_t base = (size_t)b * SS * DD + (size_t)h * DK;

    // ---- Q tile cp.async ----
    #pragma unroll
    for (int i = 0; i < 8; i++) {
        const int id   = tid + 256 * i;
        const int tile = id >> 10;
        const int r    = (id >> 3) & 127;
        const int seg  = id & 7;
        const __nv_bfloat16* g = (tile ? Ql_ : Qh_)
            + base + (size_t)(qt * 128 + r) * DD + seg * 8;
        CP16(sb + tile * QTILE_B + r * 144 + seg * 16, g);
    }
    CP_COMMIT();

    auto issueK = [&](int kt, int s) {
        const uint32_t st = kvBase + s * KVSTG;
        #pragma unroll
        for (int i = 0; i < 4; i++) {
            const int id   = tid + 256 * i;
            const int tile = id >> 9;          // 0 hi, 1 lo
            const int r    = (id >> 3) & 63;
            const int seg  = id & 7;
            const __nv_bfloat16* g = (tile ? Kl_ : Kh_)
                + base + (size_t)(kt * 64 + r) * DD + seg * 8;
            CP16(st + tile * KTILE_B + r * 144 + seg * 16, g);
        }
    };

    const int vrow = (tid & 31) * 2;
    const int dblk = tid >> 5;
    uint4 vh0, vh1, vl0, vl1;
    auto ldgV = [&](int kt) {
        const __nv_bfloat16* gh = Vh_ + base + (size_t)(kt * 64 + vrow) * DD + dblk * 8;
        const __nv_bfloat16* gl = Vl_ + base + (size_t)(kt * 64 + vrow) * DD + dblk * 8;
        vh0 = *(const uint4*)gh;  vh1 = *(const uint4*)(gh + DD);
        vl0 = *(const uint4*)gl;  vl1 = *(const uint4*)(gl + DD);
    };
    auto stsV = [&](int s) {
        const uint32_t st = kvBase + s * KVSTG;
        const uint16_t* h0p = (const uint16_t*)&vh0;
        const uint16_t* h1p = (const uint16_t*)&vh1;
        const uint16_t* l0p = (const uint16_t*)&vl0;
        const uint16_t* l1p = (const uint16_t*)&vl1;
        #pragma unroll
        for (int d = 0; d < 8; d++) {
            const uint32_t off = (uint32_t)((dblk * 8 + d) * 144 + vrow * 2);
            *(uint32_t*)(sm + (st - sb) + 2 * KTILE_B + off) =
                (uint32_t)h0p[d] | ((uint32_t)h1p[d] << 16);
            *(uint32_t*)(sm + (st - sb) + 3 * KTILE_B + off) =
                (uint32_t)l0p[d] | ((uint32_t)l1p[d] << 16);
        }
    };

    const int r0 = lane >> 2;
    unsigned char pm[2];
    pm[0] = mask[(size_t)b * SS + qt * 128 + w * 16 + r0];
    pm[1] = mask[(size_t)b * SS + qt * 128 + w * 16 + r0 + 8];

    float m_r[2] = {-1e30f, -1e30f};
    float l_r[2] = {0.f, 0.f};
    float acc_o[8][4] = {};

    const float NEGV  = -4294967295.0f;
    const float scale = 1.0f / 8.000001f;

    const int arow   = lane & 15;
    const int acb    = ((lane >> 4) * 8) * 2;
    const int qq     = lane >> 3;
    const int lr     = lane & 7;
    const int brow_q = ((qq & 2) ? 8 : 0) + lr;
    const int bcb    = ((qq & 1) * 8) * 2;

    // ---- prologue: K(0) + V(0) ----
    issueK(0, 0); CP_COMMIT();
    ldgV(0);
    CP_WAIT0();
    __syncthreads();       // Q, K0 visible
    stsV(0);

    // ---- hoist Q fragments (kt-invariant) ----
    uint32_t qfh[4][4], qfl[4][4];
    #pragma unroll
    for (int ks = 0; ks < 4; ks++) {
        const uint32_t off = (uint32_t)((w * 16 + arow) * 144 + ks * 32 + acb);
        LDSM_X4(qfh[ks][0], qfh[ks][1], qfh[ks][2], qfh[ks][3], uQh + off);
        LDSM_X4(qfl[ks][0], qfl[ks][1], qfl[ks][2], qfl[ks][3], uQl + off);
    }
    __syncthreads();       // V0 visible

    const int kmax = 2 * qt + 1;
    for (int kt = 0; kt <= kmax; kt++) {
        const int s = kt & 1;
        const uint32_t st = kvBase + s * KVSTG;
        const uint32_t uKh = st;
        const uint32_t uKl = st + KTILE_B;
        const uint32_t uVh = st + 2 * KTILE_B;
        const uint32_t uVl = st + 3 * KTILE_B;

        if (kt < kmax) {
            issueK(kt + 1, s ^ 1); CP_COMMIT();
            ldgV(kt + 1);
        }

        // ---- scores S = Q @ K^T (term-outer) ----
        float sc[8][4] = {};
        #pragma unroll
        for (int ks = 0; ks < 4; ks++) {
            const int kb = ks * 32;
            uint32_t kh[4][4], kl[4][4];
            #pragma unroll
            for (int p = 0; p < 4; p++) {
                const uint32_t off = (uint32_t)((p * 16 + brow_q) * 144 + kb + bcb);
                LDSM_X4(kh[p][0], kh[p][1], kh[p][2], kh[p][3], uKh + off);
                LDSM_X4(kl[p][0], kl[p][1], kl[p][2], kl[p][3], uKl + off);
            }
            #pragma unroll
            for (int p = 0; p < 4; p++)
                #pragma unroll
                for (int hh = 0; hh < 2; hh++)
                    mma16816(sc[p * 2 + hh], qfh[ks], &kh[p][hh * 2]);
            #pragma unroll
            for (int p = 0; p < 4; p++)
                #pragma unroll
                for (int hh = 0; hh < 2; hh++)
                    mma16816(sc[p * 2 + hh], qfh[ks], &kl[p][hh * 2]);
            #pragma unroll
            for (int p = 0; p < 4; p++)
                #pragma unroll
                for (int hh = 0; hh < 2; hh++)
                    mma16816(sc[p * 2 + hh], qfl[ks], &kh[p][hh * 2]);
        }

        // ---- scale + causal/pad mask ----
        const int qg0 = qt * 128 + w * 16 + r0;
        #pragma unroll
        for (int nt = 0; nt < 8; nt++) {
            const int cg = kt * 64 + nt * 8 + (lane & 3) * 2;
            #pragma unroll
            for (int j = 0; j < 4; j++) {
                const int row_g = (j >> 1) ? qg0 + 8 : qg0;
                const int col_g = cg + (j & 1);
                sc[nt][j] *= scale;
                if (col_g > row_g || pm[j >> 1]) sc[nt][j] = NEGV;
            }
        }

        // ---- online softmax ----
        #pragma unroll
        for (int half = 0; half < 2; half++) {
            float tm = -1e30f;
            #pragma unroll
            for (int nt = 0; nt < 8; nt++)
                tm = fmaxf(tm, fmaxf(sc[nt][half * 2], sc[nt][half * 2 + 1]));
            tm = fmaxf(tm, __shfl_xor_sync(0xffffffffu, tm, 1));
            tm = fmaxf(tm, __shfl_xor_sync(0xffffffffu, tm, 2));
            const float mn = fmaxf(m_r[half], tm);
            const float f = __expf(m_r[half] - mn);
            float ps = 0.f;
            #pragma unroll
            for (int nt = 0; nt < 8; nt++) {
                const float p0 = __expf(sc[nt][half * 2]     - mn);
                const float p1 = __expf(sc[nt][half * 2 + 1] - mn);
                sc[nt][half * 2]     = p0;
                sc[nt][half * 2 + 1] = p1;
                ps += p0 + p1;
                acc_o[nt][half * 2]     *= f;
                acc_o[nt][half * 2 + 1] *= f;
            }
            ps += __shfl_xor_sync(0xffffffffu, ps, 1);
            ps += __shfl_xor_sync(0xffffffffu, ps, 2);
            l_r[half] = l_r[half] * f + ps;
            m_r[half] = mn;
        }

        // store next V into the spare stage
        if (kt < kmax) stsV(s ^ 1);

        // ---- O += P @ V (term-outer) ----
        #pragma unroll
        for (int ks = 0; ks < 4; ks++) {
            uint32_t ph[4], pl[4];
            const int t0 = 2 * ks, t1 = 2 * ks + 1;
            split2(sc[t0][0], sc[t0][1], ph[0], pl[0]);
            split2(sc[t0][2], sc[t0][3], ph[1], pl[1]);
            split2(sc[t1][0], sc[t1][1], ph[2], pl[2]);
            split2(sc[t1][2], sc[t1][3], ph[3], pl[3]);

            const int kb = ks * 32;
            uint32_t vh[4][4], vl[4][4];
            #pragma unroll
            for (int p = 0; p < 4; p++) {
                const uint32_t off = (uint32_t)((p * 16 + brow_q) * 144 + kb + bcb);
                LDSM_X4(vh[p][0], vh[p][1], vh[p][2], vh[p][3], uVh + off);
                LDSM_X4(vl[p][0], vl[p][1], vl[p][2], vl[p][3], uVl + off);
            }
            #pragma unroll
            for (int p = 0; p < 4; p++)
                #pragma unroll
                for (int hh = 0; hh < 2; hh++)
                    mma16816(acc_o[p * 2 + hh], ph, &vh[p][hh * 2]);
            #pragma unroll
            for (int p = 0; p < 4; p++)
                #pragma unroll
                for (int hh = 0; hh < 2; hh++)
                    mma16816(acc_o[p * 2 + hh], ph, &vl[p][hh * 2]);
            #pragma unroll
            for (int p = 0; p < 4; p++)
                #pragma unroll
                for (int hh = 0; hh < 2; hh++)
                    mma16816(acc_o[p * 2 + hh], pl, &vh[p][hh * 2]);
        }

        if (kt < kmax) {
            CP_WAIT0();
            __syncthreads();
        }
    }

    // ---- normalize + write split ctx ----
    const float inv0 = 1.0f / l_r[0];
    const float inv1 = 1.0f / l_r[1];
    const int row0 = qt * 128 + w * 16 + r0;
    #pragma unroll
    for (int nt = 0; nt < 8; nt++) {
        const int col = h * DK + nt * 8 + (lane & 3) * 2;
        uint32_t hh, ll;
        split2(acc_o[nt][0] * inv0, acc_o[nt][1] * inv0, hh, ll);
        *(uint32_t*)(Ch + ((size_t)b * SS + row0) * DD + col) = hh;
        *(uint32_t*)(Cl + ((size_t)b * SS + row0) * DD + col) = ll;
        split2(acc_o[nt][2] * inv1, acc_o[nt][3] * inv1, hh, ll);
        *(uint32_t*)(Ch + ((size_t)b * SS + row0 + 8) * DD + col) = hh;
        *(uint32_t*)(Cl + ((size_t)b * SS + row0 + 8) * DD + col) = ll;
    }
}

// ---------------------------------------------------------------------------
// out = LayerNorm(X + R) * w + b ; optional split-bf16 copy of out
// ---------------------------------------------------------------------------
template<bool SPLIT>
__global__ void __launch_bounds__(256) add_ln_kernel(
    const float* __restrict__ X, const float* __restrict__ R,
    const float* __restrict__ w, const float* __restrict__ bb,
    float* __restrict__ out,
    __nv_bfloat16* __restrict__ Oh, __nv_bfloat16* __restrict__ Ol)
{
    const int row = blockIdx.x;
    const int tid = threadIdx.x;
    const float4* x4 = (const float4*)(X + (size_t)row * DD);
    const float4* r4 = (const float4*)(R + (size_t)row * DD);
    float4 v = x4[tid];
    const float4 r = r4[tid];
    v.x += r.x; v.y += r.y; v.z += r.z; v.w += r.w;

    float sum = v.x + v.y + v.z + v.w;
    float sq  = v.x*v.x + v.y*v.y + v.z*v.z + v.w*v.w;
    #pragma unroll
    for (int off = 16; off; off >>= 1) {
        sum += __shfl_xor_sync(0xffffffffu, sum, off);
        sq  += __shfl_xor_sync(0xffffffffu, sq, off);
    }
    __shared__ float ssum[8], ssq[8];
    if ((tid & 31) == 0) { ssum[tid >> 5] = sum; ssq[tid >> 5] = sq; }
    __syncthreads();
    float tot = 0.f, totq = 0.f;
    #pragma unroll
    for (int i = 0; i < 8; i++) { tot += ssum[i]; totq += ssq[i]; }
    const float mu   = tot * (1.0f / DD);
    const float var  = totq * (1.0f / DD) - mu * mu;
    const float rstd = rsqrtf(var + 1e-5f);

    const float4 wv = ((const float4*)w)[tid];
    const float4 bv = ((const float4*)bb)[tid];
    float4 ov;
    ov.x = (v.x - mu) * rstd * wv.x + bv.x;
    ov.y = (v.y - mu) * rstd * wv.y + bv.y;
    ov.z = (v.z - mu) * rstd * wv.z + bv.z;
    ov.w = (v.w - mu) * rstd * wv.w + bv.w;
    ((float4*)(out + (size_t)row * DD))[tid] = ov;
    if (SPLIT) {
        uint32_t h0, l0, h1, l1;
        split2(ov.x, ov.y, h0, l0);
        split2(ov.z, ov.w, h1, l1);
        const size_t o = (size_t)row * DD + tid * 4;
        *(uint32_t*)(Oh + o)     = h0;  *(uint32_t*)(Oh + o + 2) = h1;
        *(uint32_t*)(Ol + o)     = l0;  *(uint32_t*)(Ol + o + 2) = l1;
    }
}

// ---------------------------------------------------------------------------
extern "C" void kernel_launch(void* const* d_in, const int* in_sizes, int n_in,
                              void* d_out, int out_size)
{
    int mi = -1;
    for (int i = 0; i < n_in; i++)
        if (in_sizes[i] == BB * SS) { mi = i; break; }

    const float *Q, *K, *V, *Wq, *Wk, *Wv, *Wo, *l1w, *l1b, *l2w, *l2b, *lnw, *lnb;
    const unsigned char* mask;
    if (mi == 3) {
        Q   = (const float*)d_in[0];  K   = (const float*)d_in[1];
        V   = (const float*)d_in[2];  mask = (const unsigned char*)d_in[3];
        Wq  = (const float*)d_in[4];  Wk  = (const float*)d_in[5];
        Wv  = (const float*)d_in[6];  Wo  = (const float*)d_in[7];
        l1w = (const float*)d_in[8];  l1b = (const float*)d_in[9];
        l2w = (const float*)d_in[10]; l2b = (const float*)d_in[11];
        lnw = (const float*)d_in[12]; lnb = (const float*)d_in[13];
    } else {
        Q   = (const float*)d_in[0];  K   = (const float*)d_in[1];
        V   = (const float*)d_in[2];
        Wq  = (const float*)d_in[3];  Wk  = (const float*)d_in[4];
        Wv  = (const float*)d_in[5];  Wo  = (const float*)d_in[6];
        l1w = (const float*)d_in[7];  l1b = (const float*)d_in[8];
        l2w = (const float*)d_in[9];  l2b = (const float*)d_in[10];
        lnw = (const float*)d_in[11]; lnb = (const float*)d_in[12];
        mask = (const unsigned char*)d_in[13];
    }

    float *gA, *gB, *gC;
    __nv_bfloat16 *bf, *wsp;
    cudaGetSymbolAddress((void**)&gA, g_A);
    cudaGetSymbolAddress((void**)&gB, g_B);
    cudaGetSymbolAddress((void**)&gC, g_C);
    cudaGetSymbolAddress((void**)&bf, g_bf);
    cudaGetSymbolAddress((void**)&wsp, g_w);

    const size_t PSZ = (size_t)MTOK * DD;
    auto P = [&](int i, int half) { return bf + ((size_t)(i * 2 + half)) * PSZ; };
    const size_t WSZ = (size_t)DD * DD;
    auto W = [&](int i, int half) { return wsp + ((size_t)(i * 2 + half)) * WSZ; };

    cudaFuncSetAttribute(mma_gemm<false, false, false, true>,
                         cudaFuncAttributeMaxDynamicSharedMemorySize, GEMM_SMEM);
    cudaFuncSetAttribute(mma_gemm<false, false, true, false>,
                         cudaFuncAttributeMaxDynamicSharedMemorySize, GEMM_SMEM);
    cudaFuncSetAttribute(mma_gemm<true, true, false, true>,
                         cudaFuncAttributeMaxDynamicSharedMemorySize, GEMM_SMEM);
    cudaFuncSetAttribute(mma_gemm<true, false, true, false>,
                         cudaFuncAttributeMaxDynamicSharedMemorySize, GEMM_SMEM);
    cudaFuncSetAttribute(attn_mma_kernel,
                         cudaFuncAttributeMaxDynamicSharedMemorySize, ATT_SMEM);

    // --- converts ---
    const dim3 wtGrid(DD / 32, DD / 32);
    conv_w_t<<<wtGrid, dim3(32, 8)>>>(Wq, W(0,0), W(0,1));
    conv_w_t<<<wtGrid, dim3(32, 8)>>>(Wk, W(1,0), W(1,1));
    conv_w_t<<<wtGrid, dim3(32, 8)>>>(Wv, W(2,0), W(2,1));
    conv_w_t<<<wtGrid, dim3(32, 8)>>>(Wo, W(3,0), W(3,1));
    conv_a<<<(int)(WSZ / 1024), 256>>>(l1w, W(4,0), W(4,1));
    conv_a<<<(int)(WSZ / 1024), 256>>>(l2w, W(5,0), W(5,1));
    conv_a<<<(int)(PSZ / 1024), 256>>>(Q, P(0,0), P(0,1));
    conv_a<<<(int)(PSZ / 1024), 256>>>(K, P(1,0), P(1,1));
    conv_a<<<(int)(PSZ / 1024), 256>>>(V, P(2,0), P(2,1));

    const dim3 gGrid(DD / 128, MTOK / 128);   // (8, 128)

    // --- QKV projections -> split outputs ---
    mma_gemm<false, false, false, true><<<gGrid, 512, GEMM_SMEM>>>(
        P(0,0), P(0,1), W(0,0), W(0,1), nullptr, nullptr, P(3,0), P(3,1));   // Qp
    mma_gemm<false, false, false, true><<<gGrid, 512, GEMM_SMEM>>>(
        P(1,0), P(1,1), W(1,0), W(1,1), nullptr, nullptr, P(0,0), P(0,1));   // Kp
    mma_gemm<false, false, false, true><<<gGrid, 512, GEMM_SMEM>>>(
        P(2,0), P(2,1), W(2,0), W(2,1), nullptr, nullptr, P(1,0), P(1,1));   // Vp

    // --- attention -> split ctx ---
    attn_mma_kernel<<<dim3(SS / 128, BB * HH), 256, ATT_SMEM>>>(
        P(3,0), P(3,1), P(0,0), P(0,1), P(1,0), P(1,1), mask, P(2,0), P(2,1));

    // --- output projection -> fp32 ---
    mma_gemm<false, false, true, false><<<gGrid, 512, GEMM_SMEM>>>(
        P(2,0), P(2,1), W(3,0), W(3,1), nullptr, gA, nullptr, nullptr);

    // --- X = LN(V_att + Q): fp32 + splits ---
    add_ln_kernel<true><<<MTOK, 256>>>(gA, Q, lnw, lnb, gB, P(3,0), P(3,1));

    // --- FFN ---
    mma_gemm<true, true, false, true><<<gGrid, 512, GEMM_SMEM>>>(
        P(3,0), P(3,1), W(4,0), W(4,1), l1b, nullptr, P(0,0), P(0,1));
    mma_gemm<true, false, true, false><<<gGrid, 512, GEMM_SMEM>>>(
        P(0,0), P(0,1), W(5,0), W(5,1), l2b, gC, nullptr, nullptr);

    // --- out = LN(ffn + X) ---
    add_ln_kernel<false><<<MTOK, 256>>>(gC, gB, lnw, lnb, (float*)d_out, nullptr, nullptr);
}